// round 11
// baseline (speedup 1.0000x reference)
#include <cuda_runtime.h>
#include <stdint.h>
#include <math.h>

#define B_  2
#define S_  2048
#define D_  1024
#define H_  16
#define HD_ 64
#define MTOT (B_ * S_)           // 4096

// ---------------------------------------------------------------------------
// Scratch (__device__ globals: allocation-free rule)
// ---------------------------------------------------------------------------
__device__ float g_qkv[(size_t)B_ * S_ * 3 * D_];   // [B,S,3D] (tf32-rounded)
__device__ float g_ctx[(size_t)B_ * S_ * D_];       // [B,S,D]  (tf32-rounded)
__device__ float g_xt[(size_t)MTOT * D_];           // x, tf32-rounded
__device__ float g_wqkv_t[(size_t)3 * D_ * D_];     // W_qkv^T [3D, D]
__device__ float g_wout_t[(size_t)D_ * D_];         // W_out^T [D, D]

// ---------------------------------------------------------------------------
// Helpers (baseline-PTX only: cp.async, ldmatrix, mma.sync)
// ---------------------------------------------------------------------------
__device__ __forceinline__ uint32_t smem_u32(const void* p) {
    uint32_t a;
    asm("{ .reg .u64 t; cvta.to.shared.u64 t, %1; cvt.u32.u64 %0, t; }"
        : "=r"(a) : "l"(p));
    return a;
}
__device__ __forceinline__ float rnd_tf32(float x) {
    uint32_t u;
    asm("cvt.rna.tf32.f32 %0, %1;" : "=r"(u) : "f"(x));
    return __uint_as_float(u);
}
__device__ __forceinline__ void cp16(uint32_t dst, const void* src) {
    asm volatile("cp.async.cg.shared.global [%0], [%1], 16;"
                 :: "r"(dst), "l"(src));
}
__device__ __forceinline__ void cp_commit() {
    asm volatile("cp.async.commit_group;");
}
__device__ __forceinline__ void ldsm_x4(uint32_t addr, uint32_t* r) {
    asm volatile("ldmatrix.sync.aligned.m8n8.x4.shared.b16 {%0,%1,%2,%3}, [%4];"
                 : "=r"(r[0]), "=r"(r[1]), "=r"(r[2]), "=r"(r[3]) : "r"(addr));
}
__device__ __forceinline__ void ldsm_x2(uint32_t addr, uint32_t* r) {
    asm volatile("ldmatrix.sync.aligned.m8n8.x2.shared.b16 {%0,%1}, [%2];"
                 : "=r"(r[0]), "=r"(r[1]) : "r"(addr));
}
__device__ __forceinline__ void mma_tf32(float* c, const uint32_t* a,
                                         uint32_t b0, uint32_t b1) {
    asm volatile(
        "mma.sync.aligned.m16n8k8.row.col.f32.tf32.tf32.f32 "
        "{%0,%1,%2,%3}, {%4,%5,%6,%7}, {%8,%9}, {%0,%1,%2,%3};"
        : "+f"(c[0]), "+f"(c[1]), "+f"(c[2]), "+f"(c[3])
        : "r"(a[0]), "r"(a[1]), "r"(a[2]), "r"(a[3]), "r"(b0), "r"(b1));
}

// GEMM tile addressing: 128B rows (32 floats)
__device__ __forceinline__ uint32_t tile_addr(uint32_t base, int row, int bc) {
    return base + (uint32_t)(row * 128) + (uint32_t)(bc ^ ((row & 7) << 4));
}
// Attention tile addressing: 256B rows (64 floats), 2-level XOR swizzle
__device__ __forceinline__ uint32_t swzA(int row, int bc) {
    int nib = ((row & 7) ^ ((row >> 3) & 7)) << 4;
    return (uint32_t)(row * 256 + (bc ^ nib));
}

// ---------------------------------------------------------------------------
// Pre-pass kernels
// ---------------------------------------------------------------------------
__global__ void round_tf32_vec4(const float* __restrict__ in,
                                float* __restrict__ out, int n4) {
    int i = blockIdx.x * blockDim.x + threadIdx.x;
    if (i < n4) {
        float4 v = ((const float4*)in)[i];
        v.x = rnd_tf32(v.x); v.y = rnd_tf32(v.y);
        v.z = rnd_tf32(v.z); v.w = rnd_tf32(v.w);
        ((float4*)out)[i] = v;
    }
}

__global__ void transpose_round(const float* __restrict__ W,
                                float* __restrict__ Wt, int K, int N) {
    __shared__ float t[32][33];
    int bx = blockIdx.x * 32;
    int by = blockIdx.y * 32;
    int x = threadIdx.x, y = threadIdx.y;   // block (32, 8)
#pragma unroll
    for (int j = 0; j < 32; j += 8)
        t[y + j][x] = W[(size_t)(by + y + j) * N + bx + x];
    __syncthreads();
#pragma unroll
    for (int j = 0; j < 32; j += 8)
        Wt[(size_t)(bx + y + j) * K + by + x] = rnd_tf32(t[x][y + j]);
}

// ---------------------------------------------------------------------------
// Tensor-core tf32 GEMM + bias (mma.sync).
// 3-stage cp.async pipeline, one __syncthreads per K-iter.
// ---------------------------------------------------------------------------
#define GK    1024
#define BK    32
#define NKIT  (GK / BK)
#define STAGE_BYTES 32768
#define NSTAGE 3
#define GSMEM_BYTES (NSTAGE * STAGE_BYTES)

__global__ __launch_bounds__(256, 2)
void gemm_tc(const float* __restrict__ A, const float* __restrict__ Bt,
             const float* __restrict__ bias, float* __restrict__ C, int N,
             int do_round) {
    extern __shared__ char smem[];
    uint32_t sbase = smem_u32(smem);

    int tid  = threadIdx.x;
    int wid  = tid >> 5;
    int lane = tid & 31;
    int wm   = wid >> 2;
    int wn   = wid & 3;
    int brow = blockIdx.y * 128;
    int bcol = blockIdx.x * 128;

    uint32_t aB[NSTAGE], bB[NSTAGE];
#pragma unroll
    for (int s = 0; s < NSTAGE; s++) {
        aB[s] = sbase + s * STAGE_BYTES;
        bB[s] = aB[s] + 16384;
    }

    const float* Agp = A  + (size_t)brow * GK;
    const float* Bgp = Bt + (size_t)bcol * GK;

    int cr = tid >> 3, cc16 = (tid & 7) * 16;

    int a_row_l = ((lane >> 3) & 1) * 8 + (lane & 7);
    int a_bc_l  = (lane >> 4) * 16;
    int b_row_l = lane & 7;
    int b_bc_l  = ((lane >> 3) & 1) * 16;

    float acc[4][4][4];
#pragma unroll
    for (int i = 0; i < 4; i++)
#pragma unroll
        for (int j = 0; j < 4; j++)
#pragma unroll
            for (int k = 0; k < 4; k++) acc[i][j][k] = 0.f;

#pragma unroll
    for (int s = 0; s < 2; s++) {
        int k0 = s * BK;
#pragma unroll
        for (int j = 0; j < 4; j++) {
            int row = cr + j * 32;
            uint32_t off = tile_addr(0, row, cc16);
            cp16(aB[s] + off, Agp + (size_t)row * GK + k0 + (cc16 >> 2));
            cp16(bB[s] + off, Bgp + (size_t)row * GK + k0 + (cc16 >> 2));
        }
        cp_commit();
    }

    for (int it = 0; it < NKIT; it++) {
        if (it + 1 < NKIT) {
            asm volatile("cp.async.wait_group 1;");
        } else {
            asm volatile("cp.async.wait_group 0;");
        }
        __syncthreads();

        if (it + 2 < NKIT) {
            int s  = (it + 2) % NSTAGE;
            int k0 = (it + 2) * BK;
#pragma unroll
            for (int j = 0; j < 4; j++) {
                int row = cr + j * 32;
                uint32_t off = tile_addr(0, row, cc16);
                cp16(aB[s] + off, Agp + (size_t)row * GK + k0 + (cc16 >> 2));
                cp16(bB[s] + off, Bgp + (size_t)row * GK + k0 + (cc16 >> 2));
            }
            cp_commit();
        }

        int buf = it % NSTAGE;
        uint32_t aS = aB[buf], bS = bB[buf];
#pragma unroll
        for (int s = 0; s < 4; s++) {
            uint32_t af[4][4], bf[4][2];
#pragma unroll
            for (int mt = 0; mt < 4; mt++)
                ldsm_x4(tile_addr(aS, wm * 64 + mt * 16 + a_row_l,
                                  s * 32 + a_bc_l), af[mt]);
#pragma unroll
            for (int nt = 0; nt < 4; nt++)
                ldsm_x2(tile_addr(bS, wn * 32 + nt * 8 + b_row_l,
                                  s * 32 + b_bc_l), bf[nt]);
#pragma unroll
            for (int mt = 0; mt < 4; mt++)
#pragma unroll
                for (int nt = 0; nt < 4; nt++)
                    mma_tf32(acc[mt][nt], af[mt], bf[nt][0], bf[nt][1]);
        }
    }

#pragma unroll
    for (int mt = 0; mt < 4; mt++) {
        int r0 = brow + wm * 64 + mt * 16 + (lane >> 2);
#pragma unroll
        for (int nt = 0; nt < 4; nt++) {
            int c = bcol + wn * 32 + nt * 8 + 2 * (lane & 3);
            float b0 = bias[c], b1 = bias[c + 1];
            float v00 = acc[mt][nt][0] + b0, v01 = acc[mt][nt][1] + b1;
            float v10 = acc[mt][nt][2] + b0, v11 = acc[mt][nt][3] + b1;
            if (do_round) {
                v00 = rnd_tf32(v00); v01 = rnd_tf32(v01);
                v10 = rnd_tf32(v10); v11 = rnd_tf32(v11);
            }
            *(float2*)(C + (size_t)r0 * N + c)       = make_float2(v00, v01);
            *(float2*)(C + (size_t)(r0 + 8) * N + c) = make_float2(v10, v11);
        }
    }
}

// ---------------------------------------------------------------------------
// Tensor-core flash attention (tf32 mma.sync, online softmax).
// R4 body (x2 B-loads, direct V LDG->STS fill, minimal register footprint)
// with __launch_bounds__(256, 2): smem 96KB -> 2 CTAs/SM (192 <= 228KB),
// ~121 live regs <= 128 cap, no spills. Cross-CTA overlap hides softmax
// (MUFU), barrier waits, and V-store latency under the other CTA's HMMA.
// ---------------------------------------------------------------------------
#define ASMEM_BYTES (32768 + 2 * 16384 + 2 * 16384)

__global__ __launch_bounds__(256, 2)
void attn_tc(const float* __restrict__ qkv, float* __restrict__ ctx) {
    extern __shared__ char smem[];
    uint32_t sbase = smem_u32(smem);
    uint32_t PS    = sbase;
    uint32_t KT[2] = { sbase + 32768, sbase + 32768 + 16384 };
    uint32_t VT[2] = { sbase + 65536, sbase + 65536 + 16384 };

    int tid  = threadIdx.x;
    int wid  = tid >> 5;
    int lane = tid & 31;
    int b    = blockIdx.y >> 4;
    int h    = blockIdx.y & 15;
    int q0   = blockIdx.x * 128;

    const float* base = qkv + (size_t)b * S_ * 3 * D_ + h * HD_;
    const float scale = 0.125f;

    int a_row_l = ((lane >> 3) & 1) * 8 + (lane & 7);
    int a_bc_l  = (lane >> 4) * 16;
    int b_row_l = lane & 7;
    int b_bc_l  = ((lane >> 3) & 1) * 16;

    // ---- Q -> smem (scaled), then cache fragments in registers
    {
        for (int j = 0; j < 8; j++) {
            int idx = tid + j * 256;
            int r   = idx >> 4;
            int c16 = (idx & 15) * 16;
            float4 v = *(const float4*)(base + (size_t)(q0 + r) * (3 * D_) + (c16 >> 2));
            v.x *= scale; v.y *= scale; v.z *= scale; v.w *= scale;
            uint32_t ad = PS + swzA(r, c16);
            asm volatile("st.shared.v4.f32 [%0], {%1,%2,%3,%4};"
                         :: "r"(ad), "f"(v.x), "f"(v.y), "f"(v.z), "f"(v.w));
        }
    }
    __syncthreads();

    uint32_t qf[8][4];
#pragma unroll
    for (int ks = 0; ks < 8; ks++)
        ldsm_x4(PS + swzA(wid * 16 + a_row_l, ks * 32 + a_bc_l), qf[ks]);
    __syncthreads();   // Qs fully consumed -> becomes Ps

    float m0 = -1e30f, m1 = -1e30f, l0 = 0.f, l1 = 0.f;
    float o[8][4];
#pragma unroll
    for (int nt = 0; nt < 8; nt++)
#pragma unroll
        for (int k = 0; k < 4; k++) o[nt][k] = 0.f;

    // prologue fill: tile 0 -> buf 0
    {
        const float* kbase = base + D_;
        const float* vbase = base + 2 * D_;
#pragma unroll
        for (int j = 0; j < 4; j++) {
            int idx  = tid + j * 256;
            int krow = idx >> 4;
            int c16  = (idx & 15) * 16;
            cp16(KT[0] + swzA(krow, c16),
                 kbase + (size_t)krow * (3 * D_) + (c16 >> 2));
        }
        cp_commit();
#pragma unroll
        for (int j = 0; j < 4; j++) {
            int idx = tid + j * 256;
            int key = idx >> 4;
            int d4  = (idx & 15) * 4;
            float4 v = *(const float4*)(vbase + (size_t)key * (3 * D_) + d4);
            float vv[4] = {v.x, v.y, v.z, v.w};
#pragma unroll
            for (int e = 0; e < 4; e++) {
                uint32_t ad = VT[0] + swzA(d4 + e, key * 4);
                asm volatile("st.shared.f32 [%0], %1;" :: "r"(ad), "f"(vv[e]));
            }
        }
    }

    const int NT = S_ / 64;
    for (int kt = 0; kt < NT; kt++) {
        int buf = kt & 1;
        asm volatile("cp.async.wait_group 0;");
        __syncthreads();

        if (kt + 1 < NT) {
            int nxt = buf ^ 1;
            const float* kbase = base + (size_t)(kt + 1) * 64 * (3 * D_) + D_;
            const float* vbase = kbase + D_;
#pragma unroll
            for (int j = 0; j < 4; j++) {
                int idx  = tid + j * 256;
                int krow = idx >> 4;
                int c16  = (idx & 15) * 16;
                cp16(KT[nxt] + swzA(krow, c16),
                     kbase + (size_t)krow * (3 * D_) + (c16 >> 2));
            }
            cp_commit();
#pragma unroll
            for (int j = 0; j < 4; j++) {
                int idx = tid + j * 256;
                int key = idx >> 4;
                int d4  = (idx & 15) * 4;
                float4 v = *(const float4*)(vbase + (size_t)key * (3 * D_) + d4);
                float vv[4] = {v.x, v.y, v.z, v.w};
#pragma unroll
                for (int e = 0; e < 4; e++) {
                    uint32_t ad = VT[nxt] + swzA(d4 + e, key * 4);
                    asm volatile("st.shared.f32 [%0], %1;" :: "r"(ad), "f"(vv[e]));
                }
            }
        }

        // ---- QK^T
        float sc[8][4];
#pragma unroll
        for (int nt = 0; nt < 8; nt++)
#pragma unroll
            for (int k = 0; k < 4; k++) sc[nt][k] = 0.f;

#pragma unroll
        for (int ks = 0; ks < 8; ks++) {
            uint32_t bf[8][2];
#pragma unroll
            for (int nt = 0; nt < 8; nt++)
                ldsm_x2(KT[buf] + swzA(nt * 8 + b_row_l, ks * 32 + b_bc_l), bf[nt]);
#pragma unroll
            for (int nt = 0; nt < 8; nt++)
                mma_tf32(sc[nt], qf[ks], bf[nt][0], bf[nt][1]);
        }

        // ---- online softmax
        {
            float mt = -1e30f;
#pragma unroll
            for (int nt = 0; nt < 8; nt++)
                mt = fmaxf(mt, fmaxf(sc[nt][0], sc[nt][1]));
            mt = fmaxf(mt, __shfl_xor_sync(0xffffffffu, mt, 1));
            mt = fmaxf(mt, __shfl_xor_sync(0xffffffffu, mt, 2));
            float mn = fmaxf(m0, mt);
            float al = __expf(m0 - mn);
            m0 = mn;
            float rs = 0.f;
#pragma unroll
            for (int nt = 0; nt < 8; nt++) {
                sc[nt][0] = __expf(sc[nt][0] - mn);
                sc[nt][1] = __expf(sc[nt][1] - mn);
                rs += sc[nt][0] + sc[nt][1];
            }
            rs += __shfl_xor_sync(0xffffffffu, rs, 1);
            rs += __shfl_xor_sync(0xffffffffu, rs, 2);
            l0 = l0 * al + rs;
#pragma unroll
            for (int nt = 0; nt < 8; nt++) { o[nt][0] *= al; o[nt][1] *= al; }
        }
        {
            float mt = -1e30f;
#pragma unroll
            for (int nt = 0; nt < 8; nt++)
                mt = fmaxf(mt, fmaxf(sc[nt][2], sc[nt][3]));
            mt = fmaxf(mt, __shfl_xor_sync(0xffffffffu, mt, 1));
            mt = fmaxf(mt, __shfl_xor_sync(0xffffffffu, mt, 2));
            float mn = fmaxf(m1, mt);
            float al = __expf(m1 - mn);
            m1 = mn;
            float rs = 0.f;
#pragma unroll
            for (int nt = 0; nt < 8; nt++) {
                sc[nt][2] = __expf(sc[nt][2] - mn);
                sc[nt][3] = __expf(sc[nt][3] - mn);
                rs += sc[nt][2] + sc[nt][3];
            }
            rs += __shfl_xor_sync(0xffffffffu, rs, 1);
            rs += __shfl_xor_sync(0xffffffffu, rs, 2);
            l1 = l1 * al + rs;
#pragma unroll
            for (int nt = 0; nt < 8; nt++) { o[nt][2] *= al; o[nt][3] *= al; }
        }

        // ---- P (tf32-rounded) -> Ps (own warp's rows only)
        {
            int R0 = wid * 16 + (lane >> 2);
            int bcl = (lane & 3) * 8;
#pragma unroll
            for (int nt = 0; nt < 8; nt++) {
                uint32_t a0 = PS + swzA(R0,     nt * 32 + bcl);
                uint32_t a1 = PS + swzA(R0 + 8, nt * 32 + bcl);
                asm volatile("st.shared.v2.f32 [%0], {%1,%2};"
                             :: "r"(a0), "f"(rnd_tf32(sc[nt][0])), "f"(rnd_tf32(sc[nt][1])));
                asm volatile("st.shared.v2.f32 [%0], {%1,%2};"
                             :: "r"(a1), "f"(rnd_tf32(sc[nt][2])), "f"(rnd_tf32(sc[nt][3])));
            }
        }
        __syncwarp();

        // ---- O += P @ V
#pragma unroll
        for (int ks = 0; ks < 8; ks++) {
            uint32_t af[4];
            ldsm_x4(PS + swzA(wid * 16 + a_row_l, ks * 32 + a_bc_l), af);
            uint32_t bf[8][2];
#pragma unroll
            for (int nt = 0; nt < 8; nt++)
                ldsm_x2(VT[buf] + swzA(nt * 8 + b_row_l, ks * 32 + b_bc_l), bf[nt]);
#pragma unroll
            for (int nt = 0; nt < 8; nt++)
                mma_tf32(o[nt], af, bf[nt][0], bf[nt][1]);
        }
        __syncwarp();
    }

    // ---- epilogue
    {
        float i0 = 1.f / l0, i1 = 1.f / l1;
        int   r0 = q0 + wid * 16 + (lane >> 2);
        int   cc = h * HD_ + (lane & 3) * 2;
        float* c0 = ctx + ((size_t)b * S_ + r0) * D_ + cc;
        float* c1 = c0 + 8 * D_;
#pragma unroll
        for (int nt = 0; nt < 8; nt++) {
            *(float2*)(c0 + nt * 8) =
                make_float2(rnd_tf32(o[nt][0] * i0), rnd_tf32(o[nt][1] * i0));
            *(float2*)(c1 + nt * 8) =
                make_float2(rnd_tf32(o[nt][2] * i1), rnd_tf32(o[nt][3] * i1));
        }
    }
}

// ---------------------------------------------------------------------------
// Launch
// ---------------------------------------------------------------------------
extern "C" void kernel_launch(void* const* d_in, const int* in_sizes, int n_in,
                              void* d_out, int out_size) {
    const float* x    = (const float*)d_in[0];
    const float* Wqkv = (const float*)d_in[1];
    const float* bqkv = (const float*)d_in[2];
    const float* Wout = (const float*)d_in[3];
    const float* bout = (const float*)d_in[4];
    float* out = (float*)d_out;

    void *qkv_p, *ctx_p, *xt_p, *wq_p, *wo_p;
    cudaGetSymbolAddress(&qkv_p, g_qkv);
    cudaGetSymbolAddress(&ctx_p, g_ctx);
    cudaGetSymbolAddress(&xt_p,  g_xt);
    cudaGetSymbolAddress(&wq_p,  g_wqkv_t);
    cudaGetSymbolAddress(&wo_p,  g_wout_t);
    float* qkv   = (float*)qkv_p;
    float* ctx   = (float*)ctx_p;
    float* xt    = (float*)xt_p;
    float* wqkvt = (float*)wq_p;
    float* woutt = (float*)wo_p;

    cudaFuncSetAttribute(gemm_tc, cudaFuncAttributeMaxDynamicSharedMemorySize,
                         GSMEM_BYTES);
    cudaFuncSetAttribute(attn_tc, cudaFuncAttributeMaxDynamicSharedMemorySize,
                         ASMEM_BYTES);

    // Pre-pass
    int n4 = MTOT * D_ / 4;
    round_tf32_vec4<<<(n4 + 255) / 256, 256>>>(x, xt, n4);
    transpose_round<<<dim3(3 * D_ / 32, D_ / 32), dim3(32, 8)>>>(Wqkv, wqkvt, D_, 3 * D_);
    transpose_round<<<dim3(D_ / 32, D_ / 32), dim3(32, 8)>>>(Wout, woutt, D_, D_);

    // 1) QKV projection (round outputs -> attention consumes tf32)
    gemm_tc<<<dim3(3 * D_ / 128, MTOT / 128), 256, GSMEM_BYTES>>>(
        xt, wqkvt, bqkv, qkv, 3 * D_, 1);

    // 2) Attention (tensor-core flash, 2 CTAs/SM)
    attn_tc<<<dim3(S_ / 128, B_ * H_), 256, ASMEM_BYTES>>>(qkv, ctx);

    // 3) Output projection (no rounding — final output)
    gemm_tc<<<dim3(D_ / 128, MTOT / 128), 256, GSMEM_BYTES>>>(
        ctx, woutt, bout, out, D_, 0);
}

// round 12
// speedup vs baseline: 1.2831x; 1.2831x over previous
#include <cuda_runtime.h>
#include <stdint.h>
#include <math.h>

#define B_  2
#define S_  2048
#define D_  1024
#define H_  16
#define HD_ 64
#define MTOT (B_ * S_)           // 4096
#define NSPLIT 2
#define SKEYS (S_ / NSPLIT)      // 1024 keys per split
#define NROWS ((size_t)B_ * H_ * S_)   // 65536

// ---------------------------------------------------------------------------
// Scratch (__device__ globals: allocation-free rule)
// ---------------------------------------------------------------------------
__device__ float g_qkv[(size_t)B_ * S_ * 3 * D_];   // [B,S,3D] (tf32-rounded)
__device__ float g_xt[(size_t)MTOT * D_];           // x, tf32-rounded
__device__ float g_wqkv_t[(size_t)3 * D_ * D_];     // W_qkv^T [3D, D]
__device__ float g_wout_t[(size_t)D_ * D_];         // W_out^T [D, D]
__device__ float g_ctx[(size_t)B_ * S_ * D_];       // [B,S,D] (tf32-rounded)
// split-KV partials: [split][b][h][S] rows
__device__ float g_opart[(size_t)NSPLIT * NROWS * HD_];   // 32MB
__device__ float g_mpart[(size_t)NSPLIT * NROWS];
__device__ float g_lpart[(size_t)NSPLIT * NROWS];

// ---------------------------------------------------------------------------
// Helpers (baseline-PTX only: cp.async, ldmatrix, mma.sync)
// ---------------------------------------------------------------------------
__device__ __forceinline__ uint32_t smem_u32(const void* p) {
    uint32_t a;
    asm("{ .reg .u64 t; cvta.to.shared.u64 t, %1; cvt.u32.u64 %0, t; }"
        : "=r"(a) : "l"(p));
    return a;
}
__device__ __forceinline__ float rnd_tf32(float x) {
    uint32_t u;
    asm("cvt.rna.tf32.f32 %0, %1;" : "=r"(u) : "f"(x));
    return __uint_as_float(u);
}
__device__ __forceinline__ void cp16(uint32_t dst, const void* src) {
    asm volatile("cp.async.cg.shared.global [%0], [%1], 16;"
                 :: "r"(dst), "l"(src));
}
__device__ __forceinline__ void cp_commit() {
    asm volatile("cp.async.commit_group;");
}
__device__ __forceinline__ void ldsm_x4(uint32_t addr, uint32_t* r) {
    asm volatile("ldmatrix.sync.aligned.m8n8.x4.shared.b16 {%0,%1,%2,%3}, [%4];"
                 : "=r"(r[0]), "=r"(r[1]), "=r"(r[2]), "=r"(r[3]) : "r"(addr));
}
__device__ __forceinline__ void ldsm_x2(uint32_t addr, uint32_t* r) {
    asm volatile("ldmatrix.sync.aligned.m8n8.x2.shared.b16 {%0,%1}, [%2];"
                 : "=r"(r[0]), "=r"(r[1]) : "r"(addr));
}
__device__ __forceinline__ void mma_tf32(float* c, const uint32_t* a,
                                         uint32_t b0, uint32_t b1) {
    asm volatile(
        "mma.sync.aligned.m16n8k8.row.col.f32.tf32.tf32.f32 "
        "{%0,%1,%2,%3}, {%4,%5,%6,%7}, {%8,%9}, {%0,%1,%2,%3};"
        : "+f"(c[0]), "+f"(c[1]), "+f"(c[2]), "+f"(c[3])
        : "r"(a[0]), "r"(a[1]), "r"(a[2]), "r"(a[3]), "r"(b0), "r"(b1));
}

// GEMM tile addressing: 128B rows (32 floats)
__device__ __forceinline__ uint32_t tile_addr(uint32_t base, int row, int bc) {
    return base + (uint32_t)(row * 128) + (uint32_t)(bc ^ ((row & 7) << 4));
}
// Attention tile addressing: 256B rows (64 floats), 2-level XOR swizzle
__device__ __forceinline__ uint32_t swzA(int row, int bc) {
    int nib = ((row & 7) ^ ((row >> 3) & 7)) << 4;
    return (uint32_t)(row * 256 + (bc ^ nib));
}

// ---------------------------------------------------------------------------
// Pre-pass kernels
// ---------------------------------------------------------------------------
__global__ void round_tf32_vec4(const float* __restrict__ in,
                                float* __restrict__ out, int n4) {
    int i = blockIdx.x * blockDim.x + threadIdx.x;
    if (i < n4) {
        float4 v = ((const float4*)in)[i];
        v.x = rnd_tf32(v.x); v.y = rnd_tf32(v.y);
        v.z = rnd_tf32(v.z); v.w = rnd_tf32(v.w);
        ((float4*)out)[i] = v;
    }
}

__global__ void transpose_round(const float* __restrict__ W,
                                float* __restrict__ Wt, int K, int N) {
    __shared__ float t[32][33];
    int bx = blockIdx.x * 32;
    int by = blockIdx.y * 32;
    int x = threadIdx.x, y = threadIdx.y;   // block (32, 8)
#pragma unroll
    for (int j = 0; j < 32; j += 8)
        t[y + j][x] = W[(size_t)(by + y + j) * N + bx + x];
    __syncthreads();
#pragma unroll
    for (int j = 0; j < 32; j += 8)
        Wt[(size_t)(bx + y + j) * K + by + x] = rnd_tf32(t[x][y + j]);
}

// ---------------------------------------------------------------------------
// Tensor-core tf32 GEMM + bias (mma.sync).
// 3-stage cp.async pipeline, one __syncthreads per K-iter. (R8 version)
// ---------------------------------------------------------------------------
#define GK    1024
#define BK    32
#define NKIT  (GK / BK)
#define STAGE_BYTES 32768
#define NSTAGE 3
#define GSMEM_BYTES (NSTAGE * STAGE_BYTES)

__global__ __launch_bounds__(256, 2)
void gemm_tc(const float* __restrict__ A, const float* __restrict__ Bt,
             const float* __restrict__ bias, float* __restrict__ C, int N,
             int do_round) {
    extern __shared__ char smem[];
    uint32_t sbase = smem_u32(smem);

    int tid  = threadIdx.x;
    int wid  = tid >> 5;
    int lane = tid & 31;
    int wm   = wid >> 2;
    int wn   = wid & 3;
    int brow = blockIdx.y * 128;
    int bcol = blockIdx.x * 128;

    uint32_t aB[NSTAGE], bB[NSTAGE];
#pragma unroll
    for (int s = 0; s < NSTAGE; s++) {
        aB[s] = sbase + s * STAGE_BYTES;
        bB[s] = aB[s] + 16384;
    }

    const float* Agp = A  + (size_t)brow * GK;
    const float* Bgp = Bt + (size_t)bcol * GK;

    int cr = tid >> 3, cc16 = (tid & 7) * 16;

    int a_row_l = ((lane >> 3) & 1) * 8 + (lane & 7);
    int a_bc_l  = (lane >> 4) * 16;
    int b_row_l = lane & 7;
    int b_bc_l  = ((lane >> 3) & 1) * 16;

    float acc[4][4][4];
#pragma unroll
    for (int i = 0; i < 4; i++)
#pragma unroll
        for (int j = 0; j < 4; j++)
#pragma unroll
            for (int k = 0; k < 4; k++) acc[i][j][k] = 0.f;

#pragma unroll
    for (int s = 0; s < 2; s++) {
        int k0 = s * BK;
#pragma unroll
        for (int j = 0; j < 4; j++) {
            int row = cr + j * 32;
            uint32_t off = tile_addr(0, row, cc16);
            cp16(aB[s] + off, Agp + (size_t)row * GK + k0 + (cc16 >> 2));
            cp16(bB[s] + off, Bgp + (size_t)row * GK + k0 + (cc16 >> 2));
        }
        cp_commit();
    }

    for (int it = 0; it < NKIT; it++) {
        if (it + 1 < NKIT) {
            asm volatile("cp.async.wait_group 1;");
        } else {
            asm volatile("cp.async.wait_group 0;");
        }
        __syncthreads();

        if (it + 2 < NKIT) {
            int s  = (it + 2) % NSTAGE;
            int k0 = (it + 2) * BK;
#pragma unroll
            for (int j = 0; j < 4; j++) {
                int row = cr + j * 32;
                uint32_t off = tile_addr(0, row, cc16);
                cp16(aB[s] + off, Agp + (size_t)row * GK + k0 + (cc16 >> 2));
                cp16(bB[s] + off, Bgp + (size_t)row * GK + k0 + (cc16 >> 2));
            }
            cp_commit();
        }

        int buf = it % NSTAGE;
        uint32_t aS = aB[buf], bS = bB[buf];
#pragma unroll
        for (int s = 0; s < 4; s++) {
            uint32_t af[4][4], bf[4][2];
#pragma unroll
            for (int mt = 0; mt < 4; mt++)
                ldsm_x4(tile_addr(aS, wm * 64 + mt * 16 + a_row_l,
                                  s * 32 + a_bc_l), af[mt]);
#pragma unroll
            for (int nt = 0; nt < 4; nt++)
                ldsm_x2(tile_addr(bS, wn * 32 + nt * 8 + b_row_l,
                                  s * 32 + b_bc_l), bf[nt]);
#pragma unroll
            for (int mt = 0; mt < 4; mt++)
#pragma unroll
                for (int nt = 0; nt < 4; nt++)
                    mma_tf32(acc[mt][nt], af[mt], bf[nt][0], bf[nt][1]);
        }
    }

#pragma unroll
    for (int mt = 0; mt < 4; mt++) {
        int r0 = brow + wm * 64 + mt * 16 + (lane >> 2);
#pragma unroll
        for (int nt = 0; nt < 4; nt++) {
            int c = bcol + wn * 32 + nt * 8 + 2 * (lane & 3);
            float b0 = bias[c], b1 = bias[c + 1];
            float v00 = acc[mt][nt][0] + b0, v01 = acc[mt][nt][1] + b1;
            float v10 = acc[mt][nt][2] + b0, v11 = acc[mt][nt][3] + b1;
            if (do_round) {
                v00 = rnd_tf32(v00); v01 = rnd_tf32(v01);
                v10 = rnd_tf32(v10); v11 = rnd_tf32(v11);
            }
            *(float2*)(C + (size_t)r0 * N + c)       = make_float2(v00, v01);
            *(float2*)(C + (size_t)(r0 + 8) * N + c) = make_float2(v10, v11);
        }
    }
}

// ---------------------------------------------------------------------------
// Tensor-core flash attention, SPLIT-KV(2) (tf32 mma.sync, online softmax).
// Grid (S/128, B*H, NSPLIT), 256 threads (8 warps), occ 1, 64-key tiles,
// deferred V STS (R8 body). Split sp handles keys [sp*1024, sp*1024+1024).
// Epilogue stores UNNORMALIZED o plus per-row (m, l) to partial buffers;
// attn_combine merges the two splits.
// ---------------------------------------------------------------------------
#define ASMEM_BYTES (32768 + 2 * 16384 + 2 * 16384)

__global__ __launch_bounds__(256, 1)
void attn_tc(const float* __restrict__ qkv, float* __restrict__ op,
             float* __restrict__ mp, float* __restrict__ lp) {
    extern __shared__ char smem[];
    uint32_t sbase = smem_u32(smem);
    uint32_t PS    = sbase;
    uint32_t KT[2] = { sbase + 32768, sbase + 32768 + 16384 };
    uint32_t VT[2] = { sbase + 65536, sbase + 65536 + 16384 };

    int tid  = threadIdx.x;
    int wid  = tid >> 5;
    int lane = tid & 31;
    int b    = blockIdx.y >> 4;
    int h    = blockIdx.y & 15;
    int q0   = blockIdx.x * 128;
    int sp   = blockIdx.z;
    int key0 = sp * SKEYS;

    const float* base = qkv + (size_t)b * S_ * 3 * D_ + h * HD_;
    const float scale = 0.125f;

    int a_row_l = ((lane >> 3) & 1) * 8 + (lane & 7);
    int a_bc_l  = (lane >> 4) * 16;
    int b_row_l = lane & 7;
    int b_bc_l  = ((lane >> 3) & 1) * 16;

    // V prefetch static per-thread mapping (4 chunks/thread/tile)
    int v_key[4], v_d4[4];
#pragma unroll
    for (int j = 0; j < 4; j++) {
        int idx  = tid + j * 256;
        v_key[j] = idx >> 4;
        v_d4[j]  = (idx & 15) * 4;
    }

    // ---- Q -> smem (scaled), then cache fragments in registers
    {
        for (int j = 0; j < 8; j++) {
            int idx = tid + j * 256;
            int r   = idx >> 4;
            int c16 = (idx & 15) * 16;
            float4 v = *(const float4*)(base + (size_t)(q0 + r) * (3 * D_) + (c16 >> 2));
            v.x *= scale; v.y *= scale; v.z *= scale; v.w *= scale;
            uint32_t ad = PS + swzA(r, c16);
            asm volatile("st.shared.v4.f32 [%0], {%1,%2,%3,%4};"
                         :: "r"(ad), "f"(v.x), "f"(v.y), "f"(v.z), "f"(v.w));
        }
    }
    __syncthreads();

    uint32_t qf[8][4];
#pragma unroll
    for (int ks = 0; ks < 8; ks++)
        ldsm_x4(PS + swzA(wid * 16 + a_row_l, ks * 32 + a_bc_l), qf[ks]);
    __syncthreads();   // Qs fully consumed -> becomes Ps

    float m0 = -1e30f, m1 = -1e30f, l0 = 0.f, l1 = 0.f;
    float o[8][4];
#pragma unroll
    for (int nt = 0; nt < 8; nt++)
#pragma unroll
        for (int k = 0; k < 4; k++) o[nt][k] = 0.f;

    // prologue fill: tile 0 of this split -> buf 0
    {
        const float* kbase = base + (size_t)key0 * (3 * D_) + D_;
        const float* vbase = kbase + D_;
#pragma unroll
        for (int j = 0; j < 4; j++) {
            int idx  = tid + j * 256;
            int krow = idx >> 4;
            int c16  = (idx & 15) * 16;
            cp16(KT[0] + swzA(krow, c16),
                 kbase + (size_t)krow * (3 * D_) + (c16 >> 2));
        }
        cp_commit();
#pragma unroll
        for (int j = 0; j < 4; j++) {
            float4 v = *(const float4*)(vbase + (size_t)v_key[j] * (3 * D_) + v_d4[j]);
            float vv[4] = {v.x, v.y, v.z, v.w};
#pragma unroll
            for (int e = 0; e < 4; e++) {
                uint32_t ad = VT[0] + swzA(v_d4[j] + e, v_key[j] * 4);
                asm volatile("st.shared.f32 [%0], %1;" :: "r"(ad), "f"(vv[e]));
            }
        }
    }

    const int NT = SKEYS / 64;   // 16 tiles per split
    for (int kt = 0; kt < NT; kt++) {
        int buf = kt & 1;
        asm volatile("cp.async.wait_group 0;");
        __syncthreads();

        // ---- prefetch next tile: K via cp.async; V LDG only (STS deferred)
        float4 vreg[4];
        if (kt + 1 < NT) {
            int nxt = buf ^ 1;
            const float* kbase = base + (size_t)(key0 + (kt + 1) * 64) * (3 * D_) + D_;
            const float* vbase = kbase + D_;
#pragma unroll
            for (int j = 0; j < 4; j++) {
                int idx  = tid + j * 256;
                int krow = idx >> 4;
                int c16  = (idx & 15) * 16;
                cp16(KT[nxt] + swzA(krow, c16),
                     kbase + (size_t)krow * (3 * D_) + (c16 >> 2));
            }
            cp_commit();
#pragma unroll
            for (int j = 0; j < 4; j++)
                vreg[j] = *(const float4*)(vbase + (size_t)v_key[j] * (3 * D_) + v_d4[j]);
        }

        // ---- QK^T
        float sc[8][4];
#pragma unroll
        for (int nt = 0; nt < 8; nt++)
#pragma unroll
            for (int k = 0; k < 4; k++) sc[nt][k] = 0.f;

#pragma unroll
        for (int ks = 0; ks < 8; ks++) {
            uint32_t bf[8][2];
#pragma unroll
            for (int nt = 0; nt < 8; nt++)
                ldsm_x2(KT[buf] + swzA(nt * 8 + b_row_l, ks * 32 + b_bc_l), bf[nt]);
#pragma unroll
            for (int nt = 0; nt < 8; nt++)
                mma_tf32(sc[nt], qf[ks], bf[nt][0], bf[nt][1]);
        }

        // ---- online softmax
        {
            float mt = -1e30f;
#pragma unroll
            for (int nt = 0; nt < 8; nt++)
                mt = fmaxf(mt, fmaxf(sc[nt][0], sc[nt][1]));
            mt = fmaxf(mt, __shfl_xor_sync(0xffffffffu, mt, 1));
            mt = fmaxf(mt, __shfl_xor_sync(0xffffffffu, mt, 2));
            float mn = fmaxf(m0, mt);
            float al = __expf(m0 - mn);
            m0 = mn;
            float rs = 0.f;
#pragma unroll
            for (int nt = 0; nt < 8; nt++) {
                sc[nt][0] = __expf(sc[nt][0] - mn);
                sc[nt][1] = __expf(sc[nt][1] - mn);
                rs += sc[nt][0] + sc[nt][1];
            }
            rs += __shfl_xor_sync(0xffffffffu, rs, 1);
            rs += __shfl_xor_sync(0xffffffffu, rs, 2);
            l0 = l0 * al + rs;
#pragma unroll
            for (int nt = 0; nt < 8; nt++) { o[nt][0] *= al; o[nt][1] *= al; }
        }
        {
            float mt = -1e30f;
#pragma unroll
            for (int nt = 0; nt < 8; nt++)
                mt = fmaxf(mt, fmaxf(sc[nt][2], sc[nt][3]));
            mt = fmaxf(mt, __shfl_xor_sync(0xffffffffu, mt, 1));
            mt = fmaxf(mt, __shfl_xor_sync(0xffffffffu, mt, 2));
            float mn = fmaxf(m1, mt);
            float al = __expf(m1 - mn);
            m1 = mn;
            float rs = 0.f;
#pragma unroll
            for (int nt = 0; nt < 8; nt++) {
                sc[nt][2] = __expf(sc[nt][2] - mn);
                sc[nt][3] = __expf(sc[nt][3] - mn);
                rs += sc[nt][2] + sc[nt][3];
            }
            rs += __shfl_xor_sync(0xffffffffu, rs, 1);
            rs += __shfl_xor_sync(0xffffffffu, rs, 2);
            l1 = l1 * al + rs;
#pragma unroll
            for (int nt = 0; nt < 8; nt++) { o[nt][2] *= al; o[nt][3] *= al; }
        }

        // ---- P (tf32-rounded) -> Ps (own warp's rows only)
        {
            int R0 = wid * 16 + (lane >> 2);
            int bcl = (lane & 3) * 8;
#pragma unroll
            for (int nt = 0; nt < 8; nt++) {
                uint32_t a0 = PS + swzA(R0,     nt * 32 + bcl);
                uint32_t a1 = PS + swzA(R0 + 8, nt * 32 + bcl);
                asm volatile("st.shared.v2.f32 [%0], {%1,%2};"
                             :: "r"(a0), "f"(rnd_tf32(sc[nt][0])), "f"(rnd_tf32(sc[nt][1])));
                asm volatile("st.shared.v2.f32 [%0], {%1,%2};"
                             :: "r"(a1), "f"(rnd_tf32(sc[nt][2])), "f"(rnd_tf32(sc[nt][3])));
            }
        }
        __syncwarp();

        // ---- O += P @ V
#pragma unroll
        for (int ks = 0; ks < 8; ks++) {
            uint32_t af[4];
            ldsm_x4(PS + swzA(wid * 16 + a_row_l, ks * 32 + a_bc_l), af);
            uint32_t bf[8][2];
#pragma unroll
            for (int nt = 0; nt < 8; nt++)
                ldsm_x2(VT[buf] + swzA(nt * 8 + b_row_l, ks * 32 + b_bc_l), bf[nt]);
#pragma unroll
            for (int nt = 0; nt < 8; nt++)
                mma_tf32(o[nt], af, bf[nt][0], bf[nt][1]);
        }
        __syncwarp();

        // ---- deferred V transpose STS for next tile (ordered by next barrier)
        if (kt + 1 < NT) {
            int nxt = buf ^ 1;
#pragma unroll
            for (int j = 0; j < 4; j++) {
                float vv[4] = {vreg[j].x, vreg[j].y, vreg[j].z, vreg[j].w};
#pragma unroll
                for (int e = 0; e < 4; e++) {
                    uint32_t ad = VT[nxt] + swzA(v_d4[j] + e, v_key[j] * 4);
                    asm volatile("st.shared.f32 [%0], %1;" :: "r"(ad), "f"(vv[e]));
                }
            }
        }
    }

    // ---- epilogue: store UNNORMALIZED o + (m, l) partials
    {
        int    r0 = q0 + wid * 16 + (lane >> 2);
        size_t rowbase = (((size_t)sp * B_ + b) * H_ + h) * S_;
        size_t row0 = rowbase + r0;
        size_t row1 = rowbase + r0 + 8;
        int    cc  = (lane & 3) * 2;
        float* p0 = op + row0 * HD_ + cc;
        float* p1 = op + row1 * HD_ + cc;
#pragma unroll
        for (int nt = 0; nt < 8; nt++) {
            *(float2*)(p0 + nt * 8) = make_float2(o[nt][0], o[nt][1]);
            *(float2*)(p1 + nt * 8) = make_float2(o[nt][2], o[nt][3]);
        }
        if ((lane & 3) == 0) {
            mp[row0] = m0; lp[row0] = l0;
            mp[row1] = m1; lp[row1] = l1;
        }
    }
}

// ---------------------------------------------------------------------------
// Split-KV combine: merge 2 partial-softmax results into ctx (tf32-rounded).
// One thread per (row, float4-of-d): 65536 rows x 16 = 1M threads.
// ---------------------------------------------------------------------------
__global__ __launch_bounds__(256)
void attn_combine(const float* __restrict__ op, const float* __restrict__ mp,
                  const float* __restrict__ lp, float* __restrict__ ctx) {
    int id  = blockIdx.x * 256 + threadIdx.x;
    int row = id >> 4;                  // 0..65535 : ((b*H + h)*S + q)
    int d4  = (id & 15) * 4;

    float m0 = mp[row], m1 = mp[NROWS + row];
    float l0 = lp[row], l1 = lp[NROWS + row];
    float ms = fmaxf(m0, m1);
    float a0 = __expf(m0 - ms), a1 = __expf(m1 - ms);
    float li = 1.f / (l0 * a0 + l1 * a1);

    float4 o0 = *(const float4*)(op + (size_t)row * HD_ + d4);
    float4 o1 = *(const float4*)(op + NROWS * HD_ + (size_t)row * HD_ + d4);

    int q = row & (S_ - 1);
    int h = (row >> 11) & (H_ - 1);
    int b = row >> 15;

    float4 r;
    r.x = rnd_tf32((o0.x * a0 + o1.x * a1) * li);
    r.y = rnd_tf32((o0.y * a0 + o1.y * a1) * li);
    r.z = rnd_tf32((o0.z * a0 + o1.z * a1) * li);
    r.w = rnd_tf32((o0.w * a0 + o1.w * a1) * li);
    *(float4*)(ctx + ((size_t)b * S_ + q) * D_ + h * HD_ + d4) = r;
}

// ---------------------------------------------------------------------------
// Launch
// ---------------------------------------------------------------------------
extern "C" void kernel_launch(void* const* d_in, const int* in_sizes, int n_in,
                              void* d_out, int out_size) {
    const float* x    = (const float*)d_in[0];
    const float* Wqkv = (const float*)d_in[1];
    const float* bqkv = (const float*)d_in[2];
    const float* Wout = (const float*)d_in[3];
    const float* bout = (const float*)d_in[4];
    float* out = (float*)d_out;

    void *qkv_p, *ctx_p, *xt_p, *wq_p, *wo_p, *op_p, *mp_p, *lp_p;
    cudaGetSymbolAddress(&qkv_p, g_qkv);
    cudaGetSymbolAddress(&ctx_p, g_ctx);
    cudaGetSymbolAddress(&xt_p,  g_xt);
    cudaGetSymbolAddress(&wq_p,  g_wqkv_t);
    cudaGetSymbolAddress(&wo_p,  g_wout_t);
    cudaGetSymbolAddress(&op_p,  g_opart);
    cudaGetSymbolAddress(&mp_p,  g_mpart);
    cudaGetSymbolAddress(&lp_p,  g_lpart);
    float* qkv   = (float*)qkv_p;
    float* ctx   = (float*)ctx_p;
    float* xt    = (float*)xt_p;
    float* wqkvt = (float*)wq_p;
    float* woutt = (float*)wo_p;
    float* op    = (float*)op_p;
    float* mp    = (float*)mp_p;
    float* lp    = (float*)lp_p;

    cudaFuncSetAttribute(gemm_tc, cudaFuncAttributeMaxDynamicSharedMemorySize,
                         GSMEM_BYTES);
    cudaFuncSetAttribute(attn_tc, cudaFuncAttributeMaxDynamicSharedMemorySize,
                         ASMEM_BYTES);

    // Pre-pass
    int n4 = MTOT * D_ / 4;
    round_tf32_vec4<<<(n4 + 255) / 256, 256>>>(x, xt, n4);
    transpose_round<<<dim3(3 * D_ / 32, D_ / 32), dim3(32, 8)>>>(Wqkv, wqkvt, D_, 3 * D_);
    transpose_round<<<dim3(D_ / 32, D_ / 32), dim3(32, 8)>>>(Wout, woutt, D_, D_);

    // 1) QKV projection (round outputs -> attention consumes tf32)
    gemm_tc<<<dim3(3 * D_ / 128, MTOT / 128), 256, GSMEM_BYTES>>>(
        xt, wqkvt, bqkv, qkv, 3 * D_, 1);

    // 2) Attention (tensor-core flash, split-KV x2) + combine
    attn_tc<<<dim3(S_ / 128, B_ * H_, NSPLIT), 256, ASMEM_BYTES>>>(qkv, op, mp, lp);
    attn_combine<<<(int)(NROWS * (HD_ / 4) / 256), 256>>>(op, mp, lp, ctx);

    // 3) Output projection (no rounding — final output)
    gemm_tc<<<dim3(D_ / 128, MTOT / 128), 256, GSMEM_BYTES>>>(
        ctx, woutt, bout, out, D_, 0);
}

// round 13
// speedup vs baseline: 1.2973x; 1.0110x over previous
#include <cuda_runtime.h>
#include <stdint.h>
#include <math.h>

#define B_  2
#define S_  2048
#define D_  1024
#define H_  16
#define HD_ 64
#define MTOT (B_ * S_)           // 4096
#define NSPLIT 2
#define SKEYS (S_ / NSPLIT)      // 1024 keys per split
#define NROWS ((size_t)B_ * H_ * S_)   // 65536
#define QSCALE 0.1803368801111117f     // 0.125 * log2(e)

// ---------------------------------------------------------------------------
// Scratch (__device__ globals: allocation-free rule)
// ---------------------------------------------------------------------------
__device__ float g_qkv[(size_t)B_ * S_ * 3 * D_];   // [B,S,3D] (tf32-rounded; Q pre-scaled by QSCALE)
__device__ float g_xt[(size_t)MTOT * D_];           // x, tf32-rounded
__device__ float g_wqkv_t[(size_t)3 * D_ * D_];     // W_qkv^T [3D, D]
__device__ float g_wout_t[(size_t)D_ * D_];         // W_out^T [D, D]
__device__ float g_ctx[(size_t)B_ * S_ * D_];       // [B,S,D] (tf32-rounded)
// split-KV partials: [split][b][h][S] rows
__device__ float g_opart[(size_t)NSPLIT * NROWS * HD_];   // 32MB
__device__ float g_mpart[(size_t)NSPLIT * NROWS];
__device__ float g_lpart[(size_t)NSPLIT * NROWS];

// ---------------------------------------------------------------------------
// Helpers (baseline-PTX only: cp.async, ldmatrix, mma.sync)
// ---------------------------------------------------------------------------
__device__ __forceinline__ uint32_t smem_u32(const void* p) {
    uint32_t a;
    asm("{ .reg .u64 t; cvta.to.shared.u64 t, %1; cvt.u32.u64 %0, t; }"
        : "=r"(a) : "l"(p));
    return a;
}
__device__ __forceinline__ float rnd_tf32(float x) {
    uint32_t u;
    asm("cvt.rna.tf32.f32 %0, %1;" : "=r"(u) : "f"(x));
    return __uint_as_float(u);
}
__device__ __forceinline__ void cp16(uint32_t dst, const void* src) {
    asm volatile("cp.async.cg.shared.global [%0], [%1], 16;"
                 :: "r"(dst), "l"(src));
}
__device__ __forceinline__ void cp_commit() {
    asm volatile("cp.async.commit_group;");
}
__device__ __forceinline__ void ldsm_x4(uint32_t addr, uint32_t* r) {
    asm volatile("ldmatrix.sync.aligned.m8n8.x4.shared.b16 {%0,%1,%2,%3}, [%4];"
                 : "=r"(r[0]), "=r"(r[1]), "=r"(r[2]), "=r"(r[3]) : "r"(addr));
}
__device__ __forceinline__ void ldsm_x2(uint32_t addr, uint32_t* r) {
    asm volatile("ldmatrix.sync.aligned.m8n8.x2.shared.b16 {%0,%1}, [%2];"
                 : "=r"(r[0]), "=r"(r[1]) : "r"(addr));
}
__device__ __forceinline__ void mma_tf32(float* c, const uint32_t* a,
                                         uint32_t b0, uint32_t b1) {
    asm volatile(
        "mma.sync.aligned.m16n8k8.row.col.f32.tf32.tf32.f32 "
        "{%0,%1,%2,%3}, {%4,%5,%6,%7}, {%8,%9}, {%0,%1,%2,%3};"
        : "+f"(c[0]), "+f"(c[1]), "+f"(c[2]), "+f"(c[3])
        : "r"(a[0]), "r"(a[1]), "r"(a[2]), "r"(a[3]), "r"(b0), "r"(b1));
}

// GEMM tile addressing: 128B rows (32 floats)
__device__ __forceinline__ uint32_t tile_addr(uint32_t base, int row, int bc) {
    return base + (uint32_t)(row * 128) + (uint32_t)(bc ^ ((row & 7) << 4));
}
// Attention tile addressing: 256B rows (64 floats), 2-level XOR swizzle
__device__ __forceinline__ uint32_t swzA(int row, int bc) {
    int nib = ((row & 7) ^ ((row >> 3) & 7)) << 4;
    return (uint32_t)(row * 256 + (bc ^ nib));
}

// ---------------------------------------------------------------------------
// Pre-pass kernels
// ---------------------------------------------------------------------------
__global__ void round_tf32_vec4(const float* __restrict__ in,
                                float* __restrict__ out, int n4) {
    int i = blockIdx.x * blockDim.x + threadIdx.x;
    if (i < n4) {
        float4 v = ((const float4*)in)[i];
        v.x = rnd_tf32(v.x); v.y = rnd_tf32(v.y);
        v.z = rnd_tf32(v.z); v.w = rnd_tf32(v.w);
        ((float4*)out)[i] = v;
    }
}

__global__ void transpose_round(const float* __restrict__ W,
                                float* __restrict__ Wt, int K, int N) {
    __shared__ float t[32][33];
    int bx = blockIdx.x * 32;
    int by = blockIdx.y * 32;
    int x = threadIdx.x, y = threadIdx.y;   // block (32, 8)
#pragma unroll
    for (int j = 0; j < 32; j += 8)
        t[y + j][x] = W[(size_t)(by + y + j) * N + bx + x];
    __syncthreads();
#pragma unroll
    for (int j = 0; j < 32; j += 8)
        Wt[(size_t)(bx + y + j) * K + by + x] = rnd_tf32(t[x][y + j]);
}

// ---------------------------------------------------------------------------
// Tensor-core tf32 GEMM + bias (mma.sync).
// 3-stage cp.async pipeline, one __syncthreads per K-iter.
// mode: 0 = plain fp32 out; 1 = tf32-round out; 2 = round + scale Q columns
//       (global col < D_) by QSCALE (folds attention softmax scale + log2e).
// ---------------------------------------------------------------------------
#define GK    1024
#define BK    32
#define NKIT  (GK / BK)
#define STAGE_BYTES 32768
#define NSTAGE 3
#define GSMEM_BYTES (NSTAGE * STAGE_BYTES)

__global__ __launch_bounds__(256, 2)
void gemm_tc(const float* __restrict__ A, const float* __restrict__ Bt,
             const float* __restrict__ bias, float* __restrict__ C, int N,
             int mode) {
    extern __shared__ char smem[];
    uint32_t sbase = smem_u32(smem);

    int tid  = threadIdx.x;
    int wid  = tid >> 5;
    int lane = tid & 31;
    int wm   = wid >> 2;
    int wn   = wid & 3;
    int brow = blockIdx.y * 128;
    int bcol = blockIdx.x * 128;

    uint32_t aB[NSTAGE], bB[NSTAGE];
#pragma unroll
    for (int s = 0; s < NSTAGE; s++) {
        aB[s] = sbase + s * STAGE_BYTES;
        bB[s] = aB[s] + 16384;
    }

    const float* Agp = A  + (size_t)brow * GK;
    const float* Bgp = Bt + (size_t)bcol * GK;

    int cr = tid >> 3, cc16 = (tid & 7) * 16;

    int a_row_l = ((lane >> 3) & 1) * 8 + (lane & 7);
    int a_bc_l  = (lane >> 4) * 16;
    int b_row_l = lane & 7;
    int b_bc_l  = ((lane >> 3) & 1) * 16;

    float acc[4][4][4];
#pragma unroll
    for (int i = 0; i < 4; i++)
#pragma unroll
        for (int j = 0; j < 4; j++)
#pragma unroll
            for (int k = 0; k < 4; k++) acc[i][j][k] = 0.f;

#pragma unroll
    for (int s = 0; s < 2; s++) {
        int k0 = s * BK;
#pragma unroll
        for (int j = 0; j < 4; j++) {
            int row = cr + j * 32;
            uint32_t off = tile_addr(0, row, cc16);
            cp16(aB[s] + off, Agp + (size_t)row * GK + k0 + (cc16 >> 2));
            cp16(bB[s] + off, Bgp + (size_t)row * GK + k0 + (cc16 >> 2));
        }
        cp_commit();
    }

    for (int it = 0; it < NKIT; it++) {
        if (it + 1 < NKIT) {
            asm volatile("cp.async.wait_group 1;");
        } else {
            asm volatile("cp.async.wait_group 0;");
        }
        __syncthreads();

        if (it + 2 < NKIT) {
            int s  = (it + 2) % NSTAGE;
            int k0 = (it + 2) * BK;
#pragma unroll
            for (int j = 0; j < 4; j++) {
                int row = cr + j * 32;
                uint32_t off = tile_addr(0, row, cc16);
                cp16(aB[s] + off, Agp + (size_t)row * GK + k0 + (cc16 >> 2));
                cp16(bB[s] + off, Bgp + (size_t)row * GK + k0 + (cc16 >> 2));
            }
            cp_commit();
        }

        int buf = it % NSTAGE;
        uint32_t aS = aB[buf], bS = bB[buf];
#pragma unroll
        for (int s = 0; s < 4; s++) {
            uint32_t af[4][4], bf[4][2];
#pragma unroll
            for (int mt = 0; mt < 4; mt++)
                ldsm_x4(tile_addr(aS, wm * 64 + mt * 16 + a_row_l,
                                  s * 32 + a_bc_l), af[mt]);
#pragma unroll
            for (int nt = 0; nt < 4; nt++)
                ldsm_x2(tile_addr(bS, wn * 32 + nt * 8 + b_row_l,
                                  s * 32 + b_bc_l), bf[nt]);
#pragma unroll
            for (int mt = 0; mt < 4; mt++)
#pragma unroll
                for (int nt = 0; nt < 4; nt++)
                    mma_tf32(acc[mt][nt], af[mt], bf[nt][0], bf[nt][1]);
        }
    }

#pragma unroll
    for (int mt = 0; mt < 4; mt++) {
        int r0 = brow + wm * 64 + mt * 16 + (lane >> 2);
#pragma unroll
        for (int nt = 0; nt < 4; nt++) {
            int c = bcol + wn * 32 + nt * 8 + 2 * (lane & 3);
            float b0 = bias[c], b1 = bias[c + 1];
            float v00 = acc[mt][nt][0] + b0, v01 = acc[mt][nt][1] + b1;
            float v10 = acc[mt][nt][2] + b0, v11 = acc[mt][nt][3] + b1;
            if (mode == 2 && c < D_) {   // Q columns: fold softmax scale
                v00 *= QSCALE; v01 *= QSCALE;
                v10 *= QSCALE; v11 *= QSCALE;
            }
            if (mode >= 1) {
                v00 = rnd_tf32(v00); v01 = rnd_tf32(v01);
                v10 = rnd_tf32(v10); v11 = rnd_tf32(v11);
            }
            *(float2*)(C + (size_t)r0 * N + c)       = make_float2(v00, v01);
            *(float2*)(C + (size_t)(r0 + 8) * N + c) = make_float2(v10, v11);
        }
    }
}

// ---------------------------------------------------------------------------
// Tensor-core flash attention, SPLIT-KV(2) (tf32 mma.sync, online softmax).
// Grid (S/128, B*H, NSPLIT), 256 threads (8 warps), occ 1, 64-key tiles,
// deferred V STS. Q is pre-scaled by 0.125*log2(e) in gemm1 -> softmax uses
// bare exp2f (saves the log2e FMA inside every __expf). m/l are base-2.
// ---------------------------------------------------------------------------
#define ASMEM_BYTES (32768 + 2 * 16384 + 2 * 16384)

__global__ __launch_bounds__(256, 1)
void attn_tc(const float* __restrict__ qkv, float* __restrict__ op,
             float* __restrict__ mp, float* __restrict__ lp) {
    extern __shared__ char smem[];
    uint32_t sbase = smem_u32(smem);
    uint32_t PS    = sbase;
    uint32_t KT[2] = { sbase + 32768, sbase + 32768 + 16384 };
    uint32_t VT[2] = { sbase + 65536, sbase + 65536 + 16384 };

    int tid  = threadIdx.x;
    int wid  = tid >> 5;
    int lane = tid & 31;
    int b    = blockIdx.y >> 4;
    int h    = blockIdx.y & 15;
    int q0   = blockIdx.x * 128;
    int sp   = blockIdx.z;
    int key0 = sp * SKEYS;

    const float* base = qkv + (size_t)b * S_ * 3 * D_ + h * HD_;

    int a_row_l = ((lane >> 3) & 1) * 8 + (lane & 7);
    int a_bc_l  = (lane >> 4) * 16;
    int b_row_l = lane & 7;
    int b_bc_l  = ((lane >> 3) & 1) * 16;

    // V prefetch static per-thread mapping (4 chunks/thread/tile)
    int v_key[4], v_d4[4];
#pragma unroll
    for (int j = 0; j < 4; j++) {
        int idx  = tid + j * 256;
        v_key[j] = idx >> 4;
        v_d4[j]  = (idx & 15) * 4;
    }

    // ---- Q -> smem (pure copy; already scaled+rounded by gemm1)
    {
        for (int j = 0; j < 8; j++) {
            int idx = tid + j * 256;
            int r   = idx >> 4;
            int c16 = (idx & 15) * 16;
            float4 v = *(const float4*)(base + (size_t)(q0 + r) * (3 * D_) + (c16 >> 2));
            uint32_t ad = PS + swzA(r, c16);
            asm volatile("st.shared.v4.f32 [%0], {%1,%2,%3,%4};"
                         :: "r"(ad), "f"(v.x), "f"(v.y), "f"(v.z), "f"(v.w));
        }
    }
    __syncthreads();

    uint32_t qf[8][4];
#pragma unroll
    for (int ks = 0; ks < 8; ks++)
        ldsm_x4(PS + swzA(wid * 16 + a_row_l, ks * 32 + a_bc_l), qf[ks]);
    __syncthreads();   // Qs fully consumed -> becomes Ps

    float m0 = -1e30f, m1 = -1e30f, l0 = 0.f, l1 = 0.f;
    float o[8][4];
#pragma unroll
    for (int nt = 0; nt < 8; nt++)
#pragma unroll
        for (int k = 0; k < 4; k++) o[nt][k] = 0.f;

    // prologue fill: tile 0 of this split -> buf 0
    {
        const float* kbase = base + (size_t)key0 * (3 * D_) + D_;
        const float* vbase = kbase + D_;
#pragma unroll
        for (int j = 0; j < 4; j++) {
            int idx  = tid + j * 256;
            int krow = idx >> 4;
            int c16  = (idx & 15) * 16;
            cp16(KT[0] + swzA(krow, c16),
                 kbase + (size_t)krow * (3 * D_) + (c16 >> 2));
        }
        cp_commit();
#pragma unroll
        for (int j = 0; j < 4; j++) {
            float4 v = *(const float4*)(vbase + (size_t)v_key[j] * (3 * D_) + v_d4[j]);
            float vv[4] = {v.x, v.y, v.z, v.w};
#pragma unroll
            for (int e = 0; e < 4; e++) {
                uint32_t ad = VT[0] + swzA(v_d4[j] + e, v_key[j] * 4);
                asm volatile("st.shared.f32 [%0], %1;" :: "r"(ad), "f"(vv[e]));
            }
        }
    }

    const int NT = SKEYS / 64;   // 16 tiles per split
    for (int kt = 0; kt < NT; kt++) {
        int buf = kt & 1;
        asm volatile("cp.async.wait_group 0;");
        __syncthreads();

        // ---- prefetch next tile: K via cp.async; V LDG only (STS deferred)
        float4 vreg[4];
        if (kt + 1 < NT) {
            int nxt = buf ^ 1;
            const float* kbase = base + (size_t)(key0 + (kt + 1) * 64) * (3 * D_) + D_;
            const float* vbase = kbase + D_;
#pragma unroll
            for (int j = 0; j < 4; j++) {
                int idx  = tid + j * 256;
                int krow = idx >> 4;
                int c16  = (idx & 15) * 16;
                cp16(KT[nxt] + swzA(krow, c16),
                     kbase + (size_t)krow * (3 * D_) + (c16 >> 2));
            }
            cp_commit();
#pragma unroll
            for (int j = 0; j < 4; j++)
                vreg[j] = *(const float4*)(vbase + (size_t)v_key[j] * (3 * D_) + v_d4[j]);
        }

        // ---- QK^T
        float sc[8][4];
#pragma unroll
        for (int nt = 0; nt < 8; nt++)
#pragma unroll
            for (int k = 0; k < 4; k++) sc[nt][k] = 0.f;

#pragma unroll
        for (int ks = 0; ks < 8; ks++) {
            uint32_t bf[8][2];
#pragma unroll
            for (int nt = 0; nt < 8; nt++)
                ldsm_x2(KT[buf] + swzA(nt * 8 + b_row_l, ks * 32 + b_bc_l), bf[nt]);
#pragma unroll
            for (int nt = 0; nt < 8; nt++)
                mma_tf32(sc[nt], qf[ks], bf[nt][0], bf[nt][1]);
        }

        // ---- online softmax (base-2 domain; scores already include log2e)
        {
            float mt = -1e30f;
#pragma unroll
            for (int nt = 0; nt < 8; nt++)
                mt = fmaxf(mt, fmaxf(sc[nt][0], sc[nt][1]));
            mt = fmaxf(mt, __shfl_xor_sync(0xffffffffu, mt, 1));
            mt = fmaxf(mt, __shfl_xor_sync(0xffffffffu, mt, 2));
            float mn = fmaxf(m0, mt);
            float al = exp2f(m0 - mn);
            m0 = mn;
            float rs = 0.f;
#pragma unroll
            for (int nt = 0; nt < 8; nt++) {
                sc[nt][0] = exp2f(sc[nt][0] - mn);
                sc[nt][1] = exp2f(sc[nt][1] - mn);
                rs += sc[nt][0] + sc[nt][1];
            }
            rs += __shfl_xor_sync(0xffffffffu, rs, 1);
            rs += __shfl_xor_sync(0xffffffffu, rs, 2);
            l0 = l0 * al + rs;
#pragma unroll
            for (int nt = 0; nt < 8; nt++) { o[nt][0] *= al; o[nt][1] *= al; }
        }
        {
            float mt = -1e30f;
#pragma unroll
            for (int nt = 0; nt < 8; nt++)
                mt = fmaxf(mt, fmaxf(sc[nt][2], sc[nt][3]));
            mt = fmaxf(mt, __shfl_xor_sync(0xffffffffu, mt, 1));
            mt = fmaxf(mt, __shfl_xor_sync(0xffffffffu, mt, 2));
            float mn = fmaxf(m1, mt);
            float al = exp2f(m1 - mn);
            m1 = mn;
            float rs = 0.f;
#pragma unroll
            for (int nt = 0; nt < 8; nt++) {
                sc[nt][2] = exp2f(sc[nt][2] - mn);
                sc[nt][3] = exp2f(sc[nt][3] - mn);
                rs += sc[nt][2] + sc[nt][3];
            }
            rs += __shfl_xor_sync(0xffffffffu, rs, 1);
            rs += __shfl_xor_sync(0xffffffffu, rs, 2);
            l1 = l1 * al + rs;
#pragma unroll
            for (int nt = 0; nt < 8; nt++) { o[nt][2] *= al; o[nt][3] *= al; }
        }

        // ---- P (tf32-rounded) -> Ps (own warp's rows only)
        {
            int R0 = wid * 16 + (lane >> 2);
            int bcl = (lane & 3) * 8;
#pragma unroll
            for (int nt = 0; nt < 8; nt++) {
                uint32_t a0 = PS + swzA(R0,     nt * 32 + bcl);
                uint32_t a1 = PS + swzA(R0 + 8, nt * 32 + bcl);
                asm volatile("st.shared.v2.f32 [%0], {%1,%2};"
                             :: "r"(a0), "f"(rnd_tf32(sc[nt][0])), "f"(rnd_tf32(sc[nt][1])));
                asm volatile("st.shared.v2.f32 [%0], {%1,%2};"
                             :: "r"(a1), "f"(rnd_tf32(sc[nt][2])), "f"(rnd_tf32(sc[nt][3])));
            }
        }
        __syncwarp();

        // ---- O += P @ V
#pragma unroll
        for (int ks = 0; ks < 8; ks++) {
            uint32_t af[4];
            ldsm_x4(PS + swzA(wid * 16 + a_row_l, ks * 32 + a_bc_l), af);
            uint32_t bf[8][2];
#pragma unroll
            for (int nt = 0; nt < 8; nt++)
                ldsm_x2(VT[buf] + swzA(nt * 8 + b_row_l, ks * 32 + b_bc_l), bf[nt]);
#pragma unroll
            for (int nt = 0; nt < 8; nt++)
                mma_tf32(o[nt], af, bf[nt][0], bf[nt][1]);
        }
        __syncwarp();

        // ---- deferred V transpose STS for next tile (ordered by next barrier)
        if (kt + 1 < NT) {
            int nxt = buf ^ 1;
#pragma unroll
            for (int j = 0; j < 4; j++) {
                float vv[4] = {vreg[j].x, vreg[j].y, vreg[j].z, vreg[j].w};
#pragma unroll
                for (int e = 0; e < 4; e++) {
                    uint32_t ad = VT[nxt] + swzA(v_d4[j] + e, v_key[j] * 4);
                    asm volatile("st.shared.f32 [%0], %1;" :: "r"(ad), "f"(vv[e]));
                }
            }
        }
    }

    // ---- epilogue: store UNNORMALIZED o + (m, l) partials
    {
        int    r0 = q0 + wid * 16 + (lane >> 2);
        size_t rowbase = (((size_t)sp * B_ + b) * H_ + h) * S_;
        size_t row0 = rowbase + r0;
        size_t row1 = rowbase + r0 + 8;
        int    cc  = (lane & 3) * 2;
        float* p0 = op + row0 * HD_ + cc;
        float* p1 = op + row1 * HD_ + cc;
#pragma unroll
        for (int nt = 0; nt < 8; nt++) {
            *(float2*)(p0 + nt * 8) = make_float2(o[nt][0], o[nt][1]);
            *(float2*)(p1 + nt * 8) = make_float2(o[nt][2], o[nt][3]);
        }
        if ((lane & 3) == 0) {
            mp[row0] = m0; lp[row0] = l0;
            mp[row1] = m1; lp[row1] = l1;
        }
    }
}

// ---------------------------------------------------------------------------
// Split-KV combine: merge 2 partial-softmax results into ctx (tf32-rounded).
// m is base-2 (matches attn_tc's exp2 domain).
// ---------------------------------------------------------------------------
__global__ __launch_bounds__(256)
void attn_combine(const float* __restrict__ op, const float* __restrict__ mp,
                  const float* __restrict__ lp, float* __restrict__ ctx) {
    int id  = blockIdx.x * 256 + threadIdx.x;
    int row = id >> 4;                  // 0..65535 : ((b*H + h)*S + q)
    int d4  = (id & 15) * 4;

    float m0 = mp[row], m1 = mp[NROWS + row];
    float l0 = lp[row], l1 = lp[NROWS + row];
    float ms = fmaxf(m0, m1);
    float a0 = exp2f(m0 - ms), a1 = exp2f(m1 - ms);
    float li = 1.f / (l0 * a0 + l1 * a1);

    float4 o0 = *(const float4*)(op + (size_t)row * HD_ + d4);
    float4 o1 = *(const float4*)(op + NROWS * HD_ + (size_t)row * HD_ + d4);

    int q = row & (S_ - 1);
    int h = (row >> 11) & (H_ - 1);
    int b = row >> 15;

    float4 r;
    r.x = rnd_tf32((o0.x * a0 + o1.x * a1) * li);
    r.y = rnd_tf32((o0.y * a0 + o1.y * a1) * li);
    r.z = rnd_tf32((o0.z * a0 + o1.z * a1) * li);
    r.w = rnd_tf32((o0.w * a0 + o1.w * a1) * li);
    *(float4*)(ctx + ((size_t)b * S_ + q) * D_ + h * HD_ + d4) = r;
}

// ---------------------------------------------------------------------------
// Launch
// ---------------------------------------------------------------------------
extern "C" void kernel_launch(void* const* d_in, const int* in_sizes, int n_in,
                              void* d_out, int out_size) {
    const float* x    = (const float*)d_in[0];
    const float* Wqkv = (const float*)d_in[1];
    const float* bqkv = (const float*)d_in[2];
    const float* Wout = (const float*)d_in[3];
    const float* bout = (const float*)d_in[4];
    float* out = (float*)d_out;

    void *qkv_p, *ctx_p, *xt_p, *wq_p, *wo_p, *op_p, *mp_p, *lp_p;
    cudaGetSymbolAddress(&qkv_p, g_qkv);
    cudaGetSymbolAddress(&ctx_p, g_ctx);
    cudaGetSymbolAddress(&xt_p,  g_xt);
    cudaGetSymbolAddress(&wq_p,  g_wqkv_t);
    cudaGetSymbolAddress(&wo_p,  g_wout_t);
    cudaGetSymbolAddress(&op_p,  g_opart);
    cudaGetSymbolAddress(&mp_p,  g_mpart);
    cudaGetSymbolAddress(&lp_p,  g_lpart);
    float* qkv   = (float*)qkv_p;
    float* ctx   = (float*)ctx_p;
    float* xt    = (float*)xt_p;
    float* wqkvt = (float*)wq_p;
    float* woutt = (float*)wo_p;
    float* op    = (float*)op_p;
    float* mp    = (float*)mp_p;
    float* lp    = (float*)lp_p;

    cudaFuncSetAttribute(gemm_tc, cudaFuncAttributeMaxDynamicSharedMemorySize,
                         GSMEM_BYTES);
    cudaFuncSetAttribute(attn_tc, cudaFuncAttributeMaxDynamicSharedMemorySize,
                         ASMEM_BYTES);

    // Pre-pass
    int n4 = MTOT * D_ / 4;
    round_tf32_vec4<<<(n4 + 255) / 256, 256>>>(x, xt, n4);
    transpose_round<<<dim3(3 * D_ / 32, D_ / 32), dim3(32, 8)>>>(Wqkv, wqkvt, D_, 3 * D_);
    transpose_round<<<dim3(D_ / 32, D_ / 32), dim3(32, 8)>>>(Wout, woutt, D_, D_);

    // 1) QKV projection (round outputs; Q columns pre-scaled by 0.125*log2e)
    gemm_tc<<<dim3(3 * D_ / 128, MTOT / 128), 256, GSMEM_BYTES>>>(
        xt, wqkvt, bqkv, qkv, 3 * D_, 2);

    // 2) Attention (tensor-core flash, split-KV x2, exp2 softmax) + combine
    attn_tc<<<dim3(S_ / 128, B_ * H_, NSPLIT), 256, ASMEM_BYTES>>>(qkv, op, mp, lp);
    attn_combine<<<(int)(NROWS * (HD_ / 4) / 256), 256>>>(op, mp, lp, ctx);

    // 3) Output projection (no rounding — final output)
    gemm_tc<<<dim3(D_ / 128, MTOT / 128), 256, GSMEM_BYTES>>>(
        ctx, woutt, bout, out, D_, 0);
}

// round 14
// speedup vs baseline: 1.7410x; 1.3421x over previous
#include <cuda_runtime.h>
#include <cuda_fp16.h>
#include <stdint.h>
#include <math.h>

#define B_  2
#define S_  2048
#define D_  1024
#define H_  16
#define HD_ 64
#define MTOT (B_ * S_)           // 4096
#define NSPLIT 2
#define SKEYS (S_ / NSPLIT)      // 1024 keys per split
#define NROWS ((size_t)B_ * H_ * S_)   // 65536
#define QSCALE 0.1803368801111117f     // 0.125 * log2(e)

// ---------------------------------------------------------------------------
// Scratch (__device__ globals: allocation-free rule)
// ---------------------------------------------------------------------------
__device__ __half g_qkv16[(size_t)B_ * S_ * 3 * D_];  // fp16 qkv; Q pre-scaled
__device__ float g_xt[(size_t)MTOT * D_];             // x, tf32-rounded
__device__ float g_wqkv_t[(size_t)3 * D_ * D_];       // W_qkv^T [3D, D]
__device__ float g_wout_t[(size_t)D_ * D_];           // W_out^T [D, D]
__device__ float g_ctx[(size_t)B_ * S_ * D_];         // [B,S,D] (tf32-rounded)
// split-KV partials: [split][b][h][S] rows
__device__ float g_opart[(size_t)NSPLIT * NROWS * HD_];   // 32MB
__device__ float g_mpart[(size_t)NSPLIT * NROWS];
__device__ float g_lpart[(size_t)NSPLIT * NROWS];

// ---------------------------------------------------------------------------
// Helpers (baseline-PTX only: cp.async, ldmatrix, mma.sync)
// ---------------------------------------------------------------------------
__device__ __forceinline__ uint32_t smem_u32(const void* p) {
    uint32_t a;
    asm("{ .reg .u64 t; cvta.to.shared.u64 t, %1; cvt.u32.u64 %0, t; }"
        : "=r"(a) : "l"(p));
    return a;
}
__device__ __forceinline__ float rnd_tf32(float x) {
    uint32_t u;
    asm("cvt.rna.tf32.f32 %0, %1;" : "=r"(u) : "f"(x));
    return __uint_as_float(u);
}
__device__ __forceinline__ void cp16(uint32_t dst, const void* src) {
    asm volatile("cp.async.cg.shared.global [%0], [%1], 16;"
                 :: "r"(dst), "l"(src));
}
__device__ __forceinline__ void cp_commit() {
    asm volatile("cp.async.commit_group;");
}
__device__ __forceinline__ void ldsm_x4(uint32_t addr, uint32_t* r) {
    asm volatile("ldmatrix.sync.aligned.m8n8.x4.shared.b16 {%0,%1,%2,%3}, [%4];"
                 : "=r"(r[0]), "=r"(r[1]), "=r"(r[2]), "=r"(r[3]) : "r"(addr));
}
__device__ __forceinline__ void ldsm_x2(uint32_t addr, uint32_t* r) {
    asm volatile("ldmatrix.sync.aligned.m8n8.x2.shared.b16 {%0,%1}, [%2];"
                 : "=r"(r[0]), "=r"(r[1]) : "r"(addr));
}
__device__ __forceinline__ void ldsm_x2t(uint32_t addr, uint32_t* r) {
    asm volatile("ldmatrix.sync.aligned.m8n8.x2.trans.shared.b16 {%0,%1}, [%2];"
                 : "=r"(r[0]), "=r"(r[1]) : "r"(addr));
}
// tf32 mma (GEMMs)
__device__ __forceinline__ void mma_tf32(float* c, const uint32_t* a,
                                         uint32_t b0, uint32_t b1) {
    asm volatile(
        "mma.sync.aligned.m16n8k8.row.col.f32.tf32.tf32.f32 "
        "{%0,%1,%2,%3}, {%4,%5,%6,%7}, {%8,%9}, {%0,%1,%2,%3};"
        : "+f"(c[0]), "+f"(c[1]), "+f"(c[2]), "+f"(c[3])
        : "r"(a[0]), "r"(a[1]), "r"(a[2]), "r"(a[3]), "r"(b0), "r"(b1));
}
// fp16 mma (attention)
__device__ __forceinline__ void mma_f16(float* c, const uint32_t* a,
                                        uint32_t b0, uint32_t b1) {
    asm volatile(
        "mma.sync.aligned.m16n8k16.row.col.f32.f16.f16.f32 "
        "{%0,%1,%2,%3}, {%4,%5,%6,%7}, {%8,%9}, {%0,%1,%2,%3};"
        : "+f"(c[0]), "+f"(c[1]), "+f"(c[2]), "+f"(c[3])
        : "r"(a[0]), "r"(a[1]), "r"(a[2]), "r"(a[3]), "r"(b0), "r"(b1));
}

// 128B-row tiles (GEMM fp32 32 floats; attention fp16 64 halves)
__device__ __forceinline__ uint32_t tile_addr(uint32_t base, int row, int bc) {
    return base + (uint32_t)(row * 128) + (uint32_t)(bc ^ ((row & 7) << 4));
}

// ---------------------------------------------------------------------------
// Pre-pass kernels
// ---------------------------------------------------------------------------
__global__ void round_tf32_vec4(const float* __restrict__ in,
                                float* __restrict__ out, int n4) {
    int i = blockIdx.x * blockDim.x + threadIdx.x;
    if (i < n4) {
        float4 v = ((const float4*)in)[i];
        v.x = rnd_tf32(v.x); v.y = rnd_tf32(v.y);
        v.z = rnd_tf32(v.z); v.w = rnd_tf32(v.w);
        ((float4*)out)[i] = v;
    }
}

__global__ void transpose_round(const float* __restrict__ W,
                                float* __restrict__ Wt, int K, int N) {
    __shared__ float t[32][33];
    int bx = blockIdx.x * 32;
    int by = blockIdx.y * 32;
    int x = threadIdx.x, y = threadIdx.y;   // block (32, 8)
#pragma unroll
    for (int j = 0; j < 32; j += 8)
        t[y + j][x] = W[(size_t)(by + y + j) * N + bx + x];
    __syncthreads();
#pragma unroll
    for (int j = 0; j < 32; j += 8)
        Wt[(size_t)(bx + y + j) * K + by + x] = rnd_tf32(t[x][y + j]);
}

// ---------------------------------------------------------------------------
// Tensor-core tf32 GEMM + bias (mma.sync).
// 3-stage cp.async pipeline, one __syncthreads per K-iter.
// mode 0: fp32 C out (final). mode 2: fp16 C out, Q columns (c < D_) scaled
//         by QSCALE (folds attention softmax scale + log2e); RN cvt rounds.
// ---------------------------------------------------------------------------
#define GK    1024
#define BK    32
#define NKIT  (GK / BK)
#define STAGE_BYTES 32768
#define NSTAGE 3
#define GSMEM_BYTES (NSTAGE * STAGE_BYTES)

__global__ __launch_bounds__(256, 2)
void gemm_tc(const float* __restrict__ A, const float* __restrict__ Bt,
             const float* __restrict__ bias, void* __restrict__ Cv, int N,
             int mode) {
    extern __shared__ char smem[];
    uint32_t sbase = smem_u32(smem);

    int tid  = threadIdx.x;
    int wid  = tid >> 5;
    int lane = tid & 31;
    int wm   = wid >> 2;
    int wn   = wid & 3;
    int brow = blockIdx.y * 128;
    int bcol = blockIdx.x * 128;

    uint32_t aB[NSTAGE], bB[NSTAGE];
#pragma unroll
    for (int s = 0; s < NSTAGE; s++) {
        aB[s] = sbase + s * STAGE_BYTES;
        bB[s] = aB[s] + 16384;
    }

    const float* Agp = A  + (size_t)brow * GK;
    const float* Bgp = Bt + (size_t)bcol * GK;

    int cr = tid >> 3, cc16 = (tid & 7) * 16;

    int a_row_l = ((lane >> 3) & 1) * 8 + (lane & 7);
    int a_bc_l  = (lane >> 4) * 16;
    int b_row_l = lane & 7;
    int b_bc_l  = ((lane >> 3) & 1) * 16;

    float acc[4][4][4];
#pragma unroll
    for (int i = 0; i < 4; i++)
#pragma unroll
        for (int j = 0; j < 4; j++)
#pragma unroll
            for (int k = 0; k < 4; k++) acc[i][j][k] = 0.f;

#pragma unroll
    for (int s = 0; s < 2; s++) {
        int k0 = s * BK;
#pragma unroll
        for (int j = 0; j < 4; j++) {
            int row = cr + j * 32;
            uint32_t off = tile_addr(0, row, cc16);
            cp16(aB[s] + off, Agp + (size_t)row * GK + k0 + (cc16 >> 2));
            cp16(bB[s] + off, Bgp + (size_t)row * GK + k0 + (cc16 >> 2));
        }
        cp_commit();
    }

    for (int it = 0; it < NKIT; it++) {
        if (it + 1 < NKIT) {
            asm volatile("cp.async.wait_group 1;");
        } else {
            asm volatile("cp.async.wait_group 0;");
        }
        __syncthreads();

        if (it + 2 < NKIT) {
            int s  = (it + 2) % NSTAGE;
            int k0 = (it + 2) * BK;
#pragma unroll
            for (int j = 0; j < 4; j++) {
                int row = cr + j * 32;
                uint32_t off = tile_addr(0, row, cc16);
                cp16(aB[s] + off, Agp + (size_t)row * GK + k0 + (cc16 >> 2));
                cp16(bB[s] + off, Bgp + (size_t)row * GK + k0 + (cc16 >> 2));
            }
            cp_commit();
        }

        int buf = it % NSTAGE;
        uint32_t aS = aB[buf], bS = bB[buf];
#pragma unroll
        for (int s = 0; s < 4; s++) {
            uint32_t af[4][4], bf[4][2];
#pragma unroll
            for (int mt = 0; mt < 4; mt++)
                ldsm_x4(tile_addr(aS, wm * 64 + mt * 16 + a_row_l,
                                  s * 32 + a_bc_l), af[mt]);
#pragma unroll
            for (int nt = 0; nt < 4; nt++)
                ldsm_x2(tile_addr(bS, wn * 32 + nt * 8 + b_row_l,
                                  s * 32 + b_bc_l), bf[nt]);
#pragma unroll
            for (int mt = 0; mt < 4; mt++)
#pragma unroll
                for (int nt = 0; nt < 4; nt++)
                    mma_tf32(acc[mt][nt], af[mt], bf[nt][0], bf[nt][1]);
        }
    }

#pragma unroll
    for (int mt = 0; mt < 4; mt++) {
        int r0 = brow + wm * 64 + mt * 16 + (lane >> 2);
#pragma unroll
        for (int nt = 0; nt < 4; nt++) {
            int c = bcol + wn * 32 + nt * 8 + 2 * (lane & 3);
            float b0 = bias[c], b1 = bias[c + 1];
            float v00 = acc[mt][nt][0] + b0, v01 = acc[mt][nt][1] + b1;
            float v10 = acc[mt][nt][2] + b0, v11 = acc[mt][nt][3] + b1;
            if (mode == 2) {
                float s = (c < D_) ? QSCALE : 1.f;   // Q columns
                __half* C16 = (__half*)Cv;
                *(__half2*)(C16 + (size_t)r0 * N + c) =
                    __floats2half2_rn(v00 * s, v01 * s);
                *(__half2*)(C16 + (size_t)(r0 + 8) * N + c) =
                    __floats2half2_rn(v10 * s, v11 * s);
            } else {
                float* C = (float*)Cv;
                *(float2*)(C + (size_t)r0 * N + c)       = make_float2(v00, v01);
                *(float2*)(C + (size_t)(r0 + 8) * N + c) = make_float2(v10, v11);
            }
        }
    }
}

// ---------------------------------------------------------------------------
// FP16 tensor-core flash attention, SPLIT-KV(2), base-2 softmax.
// Grid (S/128, B*H, NSPLIT), 256 threads (8 warps), occ 1, 64-key tiles.
// m16n8k16 f16 mma: HMMA and LDSM counts halved vs tf32; V loaded via
// cp.async + ldmatrix.trans (no transpose STS). Accumulators fp32.
// smem: Q/P 16KB | K[2] 8KB ea | V[2] 8KB ea = 48KB.
// ---------------------------------------------------------------------------
#define ASMEM_BYTES (16384 + 2 * 8192 + 2 * 8192)

__global__ __launch_bounds__(256, 1)
void attn_tc(const __half* __restrict__ qkv, float* __restrict__ op,
             float* __restrict__ mp, float* __restrict__ lp) {
    extern __shared__ char smem[];
    uint32_t sbase = smem_u32(smem);
    uint32_t PS    = sbase;                                   // Q then P, 16KB
    uint32_t KT[2] = { sbase + 16384, sbase + 16384 + 8192 };
    uint32_t VT[2] = { sbase + 32768, sbase + 32768 + 8192 };

    int tid  = threadIdx.x;
    int wid  = tid >> 5;
    int lane = tid & 31;
    int b    = blockIdx.y >> 4;
    int h    = blockIdx.y & 15;
    int q0   = blockIdx.x * 128;
    int sp   = blockIdx.z;
    int key0 = sp * SKEYS;

    const __half* base = qkv + (size_t)b * S_ * 3 * D_ + h * HD_;

    int a_row_l = ((lane >> 3) & 1) * 8 + (lane & 7);
    int a_bc_l  = (lane >> 4) * 16;
    int b_row_l = lane & 7;
    int b_bc_l  = ((lane >> 3) & 1) * 16;
    int v_row_l = lane & 15;             // trans ldsm: lanes 0-15 -> 16 key rows

    // ---- Q -> smem via cp.async (128 rows x 8 chunks = 1024; 4/thread)
    {
#pragma unroll
        for (int j = 0; j < 4; j++) {
            int idx = tid + j * 256;
            int r   = idx >> 3;
            int c16 = (idx & 7) * 16;
            cp16(PS + tile_addr(0, r, c16),
                 base + (size_t)(q0 + r) * (3 * D_) + (c16 >> 1));
        }
        cp_commit();
    }
    // ---- K0/V0 fill (64 rows x 8 chunks = 512 each; 2/thread each)
    {
        const __half* kbase = base + (size_t)key0 * (3 * D_) + D_;
        const __half* vbase = kbase + D_;
#pragma unroll
        for (int j = 0; j < 2; j++) {
            int idx = tid + j * 256;
            int r   = idx >> 3;
            int c16 = (idx & 7) * 16;
            cp16(KT[0] + tile_addr(0, r, c16),
                 kbase + (size_t)r * (3 * D_) + (c16 >> 1));
            cp16(VT[0] + tile_addr(0, r, c16),
                 vbase + (size_t)r * (3 * D_) + (c16 >> 1));
        }
        cp_commit();
    }

    // Q ready (2 groups in flight; wait for all but latest)
    asm volatile("cp.async.wait_group 1;");
    __syncthreads();

    uint32_t qf[4][4];
#pragma unroll
    for (int ks = 0; ks < 4; ks++)
        ldsm_x4(PS + tile_addr(0, wid * 16 + a_row_l, ks * 32 + a_bc_l), qf[ks]);
    __syncthreads();   // Q consumed -> PS becomes P buffer

    float m0 = -1e30f, m1 = -1e30f, l0 = 0.f, l1 = 0.f;
    float o[8][4];
#pragma unroll
    for (int nt = 0; nt < 8; nt++)
#pragma unroll
        for (int k = 0; k < 4; k++) o[nt][k] = 0.f;

    const int NT = SKEYS / 64;   // 16 tiles per split
    for (int kt = 0; kt < NT; kt++) {
        int buf = kt & 1;
        asm volatile("cp.async.wait_group 0;");
        __syncthreads();

        // ---- prefetch next tile (K and V both cp.async)
        if (kt + 1 < NT) {
            int nxt = buf ^ 1;
            const __half* kbase = base + (size_t)(key0 + (kt + 1) * 64) * (3 * D_) + D_;
            const __half* vbase = kbase + D_;
#pragma unroll
            for (int j = 0; j < 2; j++) {
                int idx = tid + j * 256;
                int r   = idx >> 3;
                int c16 = (idx & 7) * 16;
                cp16(KT[nxt] + tile_addr(0, r, c16),
                     kbase + (size_t)r * (3 * D_) + (c16 >> 1));
                cp16(VT[nxt] + tile_addr(0, r, c16),
                     vbase + (size_t)r * (3 * D_) + (c16 >> 1));
            }
            cp_commit();
        }

        // ---- QK^T: 4 ks (k16) x 8 nt
        float sc[8][4];
#pragma unroll
        for (int nt = 0; nt < 8; nt++)
#pragma unroll
            for (int k = 0; k < 4; k++) sc[nt][k] = 0.f;

#pragma unroll
        for (int ks = 0; ks < 4; ks++) {
            uint32_t bf[8][2];
#pragma unroll
            for (int nt = 0; nt < 8; nt++)
                ldsm_x2(KT[buf] + tile_addr(0, nt * 8 + b_row_l,
                                            ks * 32 + b_bc_l), bf[nt]);
#pragma unroll
            for (int nt = 0; nt < 8; nt++)
                mma_f16(sc[nt], qf[ks], bf[nt][0], bf[nt][1]);
        }

        // ---- online softmax (base-2; scores already include log2e via Q)
        {
            float mt = -1e30f;
#pragma unroll
            for (int nt = 0; nt < 8; nt++)
                mt = fmaxf(mt, fmaxf(sc[nt][0], sc[nt][1]));
            mt = fmaxf(mt, __shfl_xor_sync(0xffffffffu, mt, 1));
            mt = fmaxf(mt, __shfl_xor_sync(0xffffffffu, mt, 2));
            float mn = fmaxf(m0, mt);
            float al = exp2f(m0 - mn);
            m0 = mn;
            float rs = 0.f;
#pragma unroll
            for (int nt = 0; nt < 8; nt++) {
                sc[nt][0] = exp2f(sc[nt][0] - mn);
                sc[nt][1] = exp2f(sc[nt][1] - mn);
                rs += sc[nt][0] + sc[nt][1];
            }
            rs += __shfl_xor_sync(0xffffffffu, rs, 1);
            rs += __shfl_xor_sync(0xffffffffu, rs, 2);
            l0 = l0 * al + rs;
#pragma unroll
            for (int nt = 0; nt < 8; nt++) { o[nt][0] *= al; o[nt][1] *= al; }
        }
        {
            float mt = -1e30f;
#pragma unroll
            for (int nt = 0; nt < 8; nt++)
                mt = fmaxf(mt, fmaxf(sc[nt][2], sc[nt][3]));
            mt = fmaxf(mt, __shfl_xor_sync(0xffffffffu, mt, 1));
            mt = fmaxf(mt, __shfl_xor_sync(0xffffffffu, mt, 2));
            float mn = fmaxf(m1, mt);
            float al = exp2f(m1 - mn);
            m1 = mn;
            float rs = 0.f;
#pragma unroll
            for (int nt = 0; nt < 8; nt++) {
                sc[nt][2] = exp2f(sc[nt][2] - mn);
                sc[nt][3] = exp2f(sc[nt][3] - mn);
                rs += sc[nt][2] + sc[nt][3];
            }
            rs += __shfl_xor_sync(0xffffffffu, rs, 1);
            rs += __shfl_xor_sync(0xffffffffu, rs, 2);
            l1 = l1 * al + rs;
#pragma unroll
            for (int nt = 0; nt < 8; nt++) { o[nt][2] *= al; o[nt][3] *= al; }
        }

        // ---- P (fp16) -> PS (own warp's rows; syncwarp-ordered)
        {
            int R0  = wid * 16 + (lane >> 2);
            int bcl = (lane & 3) * 4;     // bytes: 2 fp16
#pragma unroll
            for (int nt = 0; nt < 8; nt++) {
                __half2 h0 = __floats2half2_rn(sc[nt][0], sc[nt][1]);
                __half2 h1 = __floats2half2_rn(sc[nt][2], sc[nt][3]);
                uint32_t a0 = PS + tile_addr(0, R0,     nt * 16 + bcl);
                uint32_t a1 = PS + tile_addr(0, R0 + 8, nt * 16 + bcl);
                asm volatile("st.shared.b32 [%0], %1;"
                             :: "r"(a0), "r"(*(uint32_t*)&h0));
                asm volatile("st.shared.b32 [%0], %1;"
                             :: "r"(a1), "r"(*(uint32_t*)&h1));
            }
        }
        __syncwarp();

        // ---- O += P @ V : 4 ks (16 keys) x 8 nt (8 dims), V via ldsm.trans
#pragma unroll
        for (int ks = 0; ks < 4; ks++) {
            uint32_t af[4];
            ldsm_x4(PS + tile_addr(0, wid * 16 + a_row_l, ks * 32 + a_bc_l), af);
#pragma unroll
            for (int nt = 0; nt < 8; nt++) {
                uint32_t bv[2];
                ldsm_x2t(VT[buf] + tile_addr(0, ks * 16 + v_row_l, nt * 16), bv);
                mma_f16(o[nt], af, bv[0], bv[1]);
            }
        }
        __syncwarp();
    }

    // ---- epilogue: store UNNORMALIZED o + (m, l) partials
    {
        int    r0 = q0 + wid * 16 + (lane >> 2);
        size_t rowbase = (((size_t)sp * B_ + b) * H_ + h) * S_;
        size_t row0 = rowbase + r0;
        size_t row1 = rowbase + r0 + 8;
        int    cc  = (lane & 3) * 2;
        float* p0 = op + row0 * HD_ + cc;
        float* p1 = op + row1 * HD_ + cc;
#pragma unroll
        for (int nt = 0; nt < 8; nt++) {
            *(float2*)(p0 + nt * 8) = make_float2(o[nt][0], o[nt][1]);
            *(float2*)(p1 + nt * 8) = make_float2(o[nt][2], o[nt][3]);
        }
        if ((lane & 3) == 0) {
            mp[row0] = m0; lp[row0] = l0;
            mp[row1] = m1; lp[row1] = l1;
        }
    }
}

// ---------------------------------------------------------------------------
// Split-KV combine: merge 2 partial-softmax results into ctx (tf32-rounded).
// m is base-2.
// ---------------------------------------------------------------------------
__global__ __launch_bounds__(256)
void attn_combine(const float* __restrict__ op, const float* __restrict__ mp,
                  const float* __restrict__ lp, float* __restrict__ ctx) {
    int id  = blockIdx.x * 256 + threadIdx.x;
    int row = id >> 4;                  // 0..65535 : ((b*H + h)*S + q)
    int d4  = (id & 15) * 4;

    float m0 = mp[row], m1 = mp[NROWS + row];
    float l0 = lp[row], l1 = lp[NROWS + row];
    float ms = fmaxf(m0, m1);
    float a0 = exp2f(m0 - ms), a1 = exp2f(m1 - ms);
    float li = 1.f / (l0 * a0 + l1 * a1);

    float4 o0 = *(const float4*)(op + (size_t)row * HD_ + d4);
    float4 o1 = *(const float4*)(op + NROWS * HD_ + (size_t)row * HD_ + d4);

    int q = row & (S_ - 1);
    int h = (row >> 11) & (H_ - 1);
    int b = row >> 15;

    float4 r;
    r.x = rnd_tf32((o0.x * a0 + o1.x * a1) * li);
    r.y = rnd_tf32((o0.y * a0 + o1.y * a1) * li);
    r.z = rnd_tf32((o0.z * a0 + o1.z * a1) * li);
    r.w = rnd_tf32((o0.w * a0 + o1.w * a1) * li);
    *(float4*)(ctx + ((size_t)b * S_ + q) * D_ + h * HD_ + d4) = r;
}

// ---------------------------------------------------------------------------
// Launch
// ---------------------------------------------------------------------------
extern "C" void kernel_launch(void* const* d_in, const int* in_sizes, int n_in,
                              void* d_out, int out_size) {
    const float* x    = (const float*)d_in[0];
    const float* Wqkv = (const float*)d_in[1];
    const float* bqkv = (const float*)d_in[2];
    const float* Wout = (const float*)d_in[3];
    const float* bout = (const float*)d_in[4];
    float* out = (float*)d_out;

    void *qkv_p, *ctx_p, *xt_p, *wq_p, *wo_p, *op_p, *mp_p, *lp_p;
    cudaGetSymbolAddress(&qkv_p, g_qkv16);
    cudaGetSymbolAddress(&ctx_p, g_ctx);
    cudaGetSymbolAddress(&xt_p,  g_xt);
    cudaGetSymbolAddress(&wq_p,  g_wqkv_t);
    cudaGetSymbolAddress(&wo_p,  g_wout_t);
    cudaGetSymbolAddress(&op_p,  g_opart);
    cudaGetSymbolAddress(&mp_p,  g_mpart);
    cudaGetSymbolAddress(&lp_p,  g_lpart);
    __half* qkv16 = (__half*)qkv_p;
    float* ctx   = (float*)ctx_p;
    float* xt    = (float*)xt_p;
    float* wqkvt = (float*)wq_p;
    float* woutt = (float*)wo_p;
    float* op    = (float*)op_p;
    float* mp    = (float*)mp_p;
    float* lp    = (float*)lp_p;

    cudaFuncSetAttribute(gemm_tc, cudaFuncAttributeMaxDynamicSharedMemorySize,
                         GSMEM_BYTES);
    cudaFuncSetAttribute(attn_tc, cudaFuncAttributeMaxDynamicSharedMemorySize,
                         ASMEM_BYTES);

    // Pre-pass
    int n4 = MTOT * D_ / 4;
    round_tf32_vec4<<<(n4 + 255) / 256, 256>>>(x, xt, n4);
    transpose_round<<<dim3(3 * D_ / 32, D_ / 32), dim3(32, 8)>>>(Wqkv, wqkvt, D_, 3 * D_);
    transpose_round<<<dim3(D_ / 32, D_ / 32), dim3(32, 8)>>>(Wout, woutt, D_, D_);

    // 1) QKV projection -> fp16 qkv (Q pre-scaled by 0.125*log2e)
    gemm_tc<<<dim3(3 * D_ / 128, MTOT / 128), 256, GSMEM_BYTES>>>(
        xt, wqkvt, bqkv, qkv16, 3 * D_, 2);

    // 2) Attention (fp16 tensor-core flash, split-KV x2) + combine
    attn_tc<<<dim3(S_ / 128, B_ * H_, NSPLIT), 256, ASMEM_BYTES>>>(qkv16, op, mp, lp);
    attn_combine<<<(int)(NROWS * (HD_ / 4) / 256), 256>>>(op, mp, lp, ctx);

    // 3) Output projection (tf32, fp32 out)
    gemm_tc<<<dim3(D_ / 128, MTOT / 128), 256, GSMEM_BYTES>>>(
        ctx, woutt, bout, out, D_, 0);
}

// round 15
// speedup vs baseline: 2.3166x; 1.3306x over previous
#include <cuda_runtime.h>
#include <cuda_fp16.h>
#include <stdint.h>
#include <math.h>

#define B_  2
#define S_  2048
#define D_  1024
#define H_  16
#define HD_ 64
#define MTOT (B_ * S_)           // 4096
#define NSPLIT 2
#define SKEYS (S_ / NSPLIT)      // 1024 keys per split
#define NROWS ((size_t)B_ * H_ * S_)   // 65536
#define QSCALE 0.1803368801111117f     // 0.125 * log2(e)

// ---------------------------------------------------------------------------
// Scratch (__device__ globals: allocation-free rule)
// ---------------------------------------------------------------------------
__device__ __half g_qkv16[(size_t)B_ * S_ * 3 * D_];  // fp16 qkv; Q pre-scaled
__device__ __half g_x16[(size_t)MTOT * D_];           // x, fp16
__device__ __half g_wqkv_t16[(size_t)3 * D_ * D_];    // W_qkv^T [3D, D] fp16
__device__ __half g_wout_t16[(size_t)D_ * D_];        // W_out^T [D, D] fp16
__device__ __half g_ctx16[(size_t)B_ * S_ * D_];      // [B,S,D] fp16
// split-KV partials: [split][b][h][S] rows
__device__ float g_opart[(size_t)NSPLIT * NROWS * HD_];   // 32MB
__device__ float g_mpart[(size_t)NSPLIT * NROWS];
__device__ float g_lpart[(size_t)NSPLIT * NROWS];

// ---------------------------------------------------------------------------
// Helpers (baseline-PTX only: cp.async, ldmatrix, mma.sync)
// ---------------------------------------------------------------------------
__device__ __forceinline__ uint32_t smem_u32(const void* p) {
    uint32_t a;
    asm("{ .reg .u64 t; cvta.to.shared.u64 t, %1; cvt.u32.u64 %0, t; }"
        : "=r"(a) : "l"(p));
    return a;
}
__device__ __forceinline__ void cp16(uint32_t dst, const void* src) {
    asm volatile("cp.async.cg.shared.global [%0], [%1], 16;"
                 :: "r"(dst), "l"(src));
}
__device__ __forceinline__ void cp_commit() {
    asm volatile("cp.async.commit_group;");
}
__device__ __forceinline__ void ldsm_x4(uint32_t addr, uint32_t* r) {
    asm volatile("ldmatrix.sync.aligned.m8n8.x4.shared.b16 {%0,%1,%2,%3}, [%4];"
                 : "=r"(r[0]), "=r"(r[1]), "=r"(r[2]), "=r"(r[3]) : "r"(addr));
}
__device__ __forceinline__ void ldsm_x2(uint32_t addr, uint32_t* r) {
    asm volatile("ldmatrix.sync.aligned.m8n8.x2.shared.b16 {%0,%1}, [%2];"
                 : "=r"(r[0]), "=r"(r[1]) : "r"(addr));
}
__device__ __forceinline__ void ldsm_x2t(uint32_t addr, uint32_t* r) {
    asm volatile("ldmatrix.sync.aligned.m8n8.x2.trans.shared.b16 {%0,%1}, [%2];"
                 : "=r"(r[0]), "=r"(r[1]) : "r"(addr));
}
__device__ __forceinline__ void mma_f16(float* c, const uint32_t* a,
                                        uint32_t b0, uint32_t b1) {
    asm volatile(
        "mma.sync.aligned.m16n8k16.row.col.f32.f16.f16.f32 "
        "{%0,%1,%2,%3}, {%4,%5,%6,%7}, {%8,%9}, {%0,%1,%2,%3};"
        : "+f"(c[0]), "+f"(c[1]), "+f"(c[2]), "+f"(c[3])
        : "r"(a[0]), "r"(a[1]), "r"(a[2]), "r"(a[3]), "r"(b0), "r"(b1));
}

// 128B-row tiles (fp16: 64 halves per row)
__device__ __forceinline__ uint32_t tile_addr(uint32_t base, int row, int bc) {
    return base + (uint32_t)(row * 128) + (uint32_t)(bc ^ ((row & 7) << 4));
}

// ---------------------------------------------------------------------------
// Pre-pass kernels: fp32 -> fp16 (RN), and transpose+convert for weights
// ---------------------------------------------------------------------------
__global__ void to_half4(const float* __restrict__ in,
                         __half* __restrict__ out, int n4) {
    int i = blockIdx.x * blockDim.x + threadIdx.x;
    if (i < n4) {
        float4 v = ((const float4*)in)[i];
        __half2 h0 = __floats2half2_rn(v.x, v.y);
        __half2 h1 = __floats2half2_rn(v.z, v.w);
        uint2 u;
        u.x = *(uint32_t*)&h0;
        u.y = *(uint32_t*)&h1;
        ((uint2*)out)[i] = u;
    }
}

// W: [K,N] f32 row-major -> Wt: [N,K] fp16 row-major
__global__ void transpose_half(const float* __restrict__ W,
                               __half* __restrict__ Wt, int K, int N) {
    __shared__ float t[32][33];
    int bx = blockIdx.x * 32;
    int by = blockIdx.y * 32;
    int x = threadIdx.x, y = threadIdx.y;   // block (32, 8)
#pragma unroll
    for (int j = 0; j < 32; j += 8)
        t[y + j][x] = W[(size_t)(by + y + j) * N + bx + x];
    __syncthreads();
#pragma unroll
    for (int j = 0; j < 32; j += 8)
        Wt[(size_t)(bx + y + j) * K + by + x] = __float2half_rn(t[x][y + j]);
}

// ---------------------------------------------------------------------------
// FP16 tensor-core GEMM + bias (m16n8k16, fp32 accum).
// C[M,N] = A[M,K] @ Bt[N,K]^T + bias.  K = 1024 fp16.
// Tile 128x128, BK=64 halves (128B rows), 3-stage cp.async, 1 barrier/iter.
// mode 0: fp32 C out (final). mode 2: fp16 C out, Q cols (c<D_) * QSCALE.
// ---------------------------------------------------------------------------
#define GK    1024
#define BKH   64
#define NKIT  (GK / BKH)         // 16
#define STAGE_BYTES 32768        // A 16KB + B 16KB
#define NSTAGE 3
#define GSMEM_BYTES (NSTAGE * STAGE_BYTES)

__global__ __launch_bounds__(256, 2)
void gemm_f16(const __half* __restrict__ A, const __half* __restrict__ Bt,
              const float* __restrict__ bias, void* __restrict__ Cv, int N,
              int mode) {
    extern __shared__ char smem[];
    uint32_t sbase = smem_u32(smem);

    int tid  = threadIdx.x;
    int wid  = tid >> 5;
    int lane = tid & 31;
    int wm   = wid >> 2;
    int wn   = wid & 3;
    int brow = blockIdx.y * 128;
    int bcol = blockIdx.x * 128;

    uint32_t aB[NSTAGE], bB[NSTAGE];
#pragma unroll
    for (int s = 0; s < NSTAGE; s++) {
        aB[s] = sbase + s * STAGE_BYTES;
        bB[s] = aB[s] + 16384;
    }

    const __half* Agp = A  + (size_t)brow * GK;
    const __half* Bgp = Bt + (size_t)bcol * GK;

    // chunk map: 1024 chunks per tile (128 rows x 8), 4/thread per tile
    int cr = tid >> 1, cc16a = (tid & 1) * 16;   // unused split helper
    (void)cr; (void)cc16a;

    int a_row_l = ((lane >> 3) & 1) * 8 + (lane & 7);
    int a_bc_l  = (lane >> 4) * 16;
    int b_row_l = lane & 7;
    int b_bc_l  = ((lane >> 3) & 1) * 16;

    float acc[4][4][4];
#pragma unroll
    for (int i = 0; i < 4; i++)
#pragma unroll
        for (int j = 0; j < 4; j++)
#pragma unroll
            for (int k = 0; k < 4; k++) acc[i][j][k] = 0.f;

#pragma unroll
    for (int s = 0; s < 2; s++) {
        int k0 = s * BKH;
#pragma unroll
        for (int j = 0; j < 4; j++) {
            int idx = tid + j * 256;
            int row = idx >> 3;
            int c16 = (idx & 7) * 16;
            uint32_t off = tile_addr(0, row, c16);
            cp16(aB[s] + off, Agp + (size_t)row * GK + k0 + (c16 >> 1));
            cp16(bB[s] + off, Bgp + (size_t)row * GK + k0 + (c16 >> 1));
        }
        cp_commit();
    }

    for (int it = 0; it < NKIT; it++) {
        if (it + 1 < NKIT) {
            asm volatile("cp.async.wait_group 1;");
        } else {
            asm volatile("cp.async.wait_group 0;");
        }
        __syncthreads();

        if (it + 2 < NKIT) {
            int s  = (it + 2) % NSTAGE;
            int k0 = (it + 2) * BKH;
#pragma unroll
            for (int j = 0; j < 4; j++) {
                int idx = tid + j * 256;
                int row = idx >> 3;
                int c16 = (idx & 7) * 16;
                uint32_t off = tile_addr(0, row, c16);
                cp16(aB[s] + off, Agp + (size_t)row * GK + k0 + (c16 >> 1));
                cp16(bB[s] + off, Bgp + (size_t)row * GK + k0 + (c16 >> 1));
            }
            cp_commit();
        }

        int buf = it % NSTAGE;
        uint32_t aS = aB[buf], bS = bB[buf];
#pragma unroll
        for (int ks = 0; ks < 4; ks++) {
            uint32_t af[4][4], bf[4][2];
#pragma unroll
            for (int mt = 0; mt < 4; mt++)
                ldsm_x4(tile_addr(aS, wm * 64 + mt * 16 + a_row_l,
                                  ks * 32 + a_bc_l), af[mt]);
#pragma unroll
            for (int nt = 0; nt < 4; nt++)
                ldsm_x2(tile_addr(bS, wn * 32 + nt * 8 + b_row_l,
                                  ks * 32 + b_bc_l), bf[nt]);
#pragma unroll
            for (int mt = 0; mt < 4; mt++)
#pragma unroll
                for (int nt = 0; nt < 4; nt++)
                    mma_f16(acc[mt][nt], af[mt], bf[nt][0], bf[nt][1]);
        }
    }

#pragma unroll
    for (int mt = 0; mt < 4; mt++) {
        int r0 = brow + wm * 64 + mt * 16 + (lane >> 2);
#pragma unroll
        for (int nt = 0; nt < 4; nt++) {
            int c = bcol + wn * 32 + nt * 8 + 2 * (lane & 3);
            float b0 = bias[c], b1 = bias[c + 1];
            float v00 = acc[mt][nt][0] + b0, v01 = acc[mt][nt][1] + b1;
            float v10 = acc[mt][nt][2] + b0, v11 = acc[mt][nt][3] + b1;
            if (mode == 2) {
                float s = (c < D_) ? QSCALE : 1.f;   // Q columns
                __half* C16 = (__half*)Cv;
                *(__half2*)(C16 + (size_t)r0 * N + c) =
                    __floats2half2_rn(v00 * s, v01 * s);
                *(__half2*)(C16 + (size_t)(r0 + 8) * N + c) =
                    __floats2half2_rn(v10 * s, v11 * s);
            } else {
                float* C = (float*)Cv;
                *(float2*)(C + (size_t)r0 * N + c)       = make_float2(v00, v01);
                *(float2*)(C + (size_t)(r0 + 8) * N + c) = make_float2(v10, v11);
            }
        }
    }
}

// ---------------------------------------------------------------------------
// FP16 tensor-core flash attention, SPLIT-KV(2), base-2 softmax. (R14)
// ---------------------------------------------------------------------------
#define ASMEM_BYTES (16384 + 2 * 8192 + 2 * 8192)

__global__ __launch_bounds__(256, 1)
void attn_tc(const __half* __restrict__ qkv, float* __restrict__ op,
             float* __restrict__ mp, float* __restrict__ lp) {
    extern __shared__ char smem[];
    uint32_t sbase = smem_u32(smem);
    uint32_t PS    = sbase;                                   // Q then P, 16KB
    uint32_t KT[2] = { sbase + 16384, sbase + 16384 + 8192 };
    uint32_t VT[2] = { sbase + 32768, sbase + 32768 + 8192 };

    int tid  = threadIdx.x;
    int wid  = tid >> 5;
    int lane = tid & 31;
    int b    = blockIdx.y >> 4;
    int h    = blockIdx.y & 15;
    int q0   = blockIdx.x * 128;
    int sp   = blockIdx.z;
    int key0 = sp * SKEYS;

    const __half* base = qkv + (size_t)b * S_ * 3 * D_ + h * HD_;

    int a_row_l = ((lane >> 3) & 1) * 8 + (lane & 7);
    int a_bc_l  = (lane >> 4) * 16;
    int b_row_l = lane & 7;
    int b_bc_l  = ((lane >> 3) & 1) * 16;
    int v_row_l = lane & 15;

    // ---- Q -> smem via cp.async (128 rows x 8 chunks = 1024; 4/thread)
    {
#pragma unroll
        for (int j = 0; j < 4; j++) {
            int idx = tid + j * 256;
            int r   = idx >> 3;
            int c16 = (idx & 7) * 16;
            cp16(PS + tile_addr(0, r, c16),
                 base + (size_t)(q0 + r) * (3 * D_) + (c16 >> 1));
        }
        cp_commit();
    }
    // ---- K0/V0 fill
    {
        const __half* kbase = base + (size_t)key0 * (3 * D_) + D_;
        const __half* vbase = kbase + D_;
#pragma unroll
        for (int j = 0; j < 2; j++) {
            int idx = tid + j * 256;
            int r   = idx >> 3;
            int c16 = (idx & 7) * 16;
            cp16(KT[0] + tile_addr(0, r, c16),
                 kbase + (size_t)r * (3 * D_) + (c16 >> 1));
            cp16(VT[0] + tile_addr(0, r, c16),
                 vbase + (size_t)r * (3 * D_) + (c16 >> 1));
        }
        cp_commit();
    }

    asm volatile("cp.async.wait_group 1;");
    __syncthreads();

    uint32_t qf[4][4];
#pragma unroll
    for (int ks = 0; ks < 4; ks++)
        ldsm_x4(PS + tile_addr(0, wid * 16 + a_row_l, ks * 32 + a_bc_l), qf[ks]);
    __syncthreads();

    float m0 = -1e30f, m1 = -1e30f, l0 = 0.f, l1 = 0.f;
    float o[8][4];
#pragma unroll
    for (int nt = 0; nt < 8; nt++)
#pragma unroll
        for (int k = 0; k < 4; k++) o[nt][k] = 0.f;

    const int NT = SKEYS / 64;
    for (int kt = 0; kt < NT; kt++) {
        int buf = kt & 1;
        asm volatile("cp.async.wait_group 0;");
        __syncthreads();

        if (kt + 1 < NT) {
            int nxt = buf ^ 1;
            const __half* kbase = base + (size_t)(key0 + (kt + 1) * 64) * (3 * D_) + D_;
            const __half* vbase = kbase + D_;
#pragma unroll
            for (int j = 0; j < 2; j++) {
                int idx = tid + j * 256;
                int r   = idx >> 3;
                int c16 = (idx & 7) * 16;
                cp16(KT[nxt] + tile_addr(0, r, c16),
                     kbase + (size_t)r * (3 * D_) + (c16 >> 1));
                cp16(VT[nxt] + tile_addr(0, r, c16),
                     vbase + (size_t)r * (3 * D_) + (c16 >> 1));
            }
            cp_commit();
        }

        float sc[8][4];
#pragma unroll
        for (int nt = 0; nt < 8; nt++)
#pragma unroll
            for (int k = 0; k < 4; k++) sc[nt][k] = 0.f;

#pragma unroll
        for (int ks = 0; ks < 4; ks++) {
            uint32_t bf[8][2];
#pragma unroll
            for (int nt = 0; nt < 8; nt++)
                ldsm_x2(KT[buf] + tile_addr(0, nt * 8 + b_row_l,
                                            ks * 32 + b_bc_l), bf[nt]);
#pragma unroll
            for (int nt = 0; nt < 8; nt++)
                mma_f16(sc[nt], qf[ks], bf[nt][0], bf[nt][1]);
        }

        {
            float mt = -1e30f;
#pragma unroll
            for (int nt = 0; nt < 8; nt++)
                mt = fmaxf(mt, fmaxf(sc[nt][0], sc[nt][1]));
            mt = fmaxf(mt, __shfl_xor_sync(0xffffffffu, mt, 1));
            mt = fmaxf(mt, __shfl_xor_sync(0xffffffffu, mt, 2));
            float mn = fmaxf(m0, mt);
            float al = exp2f(m0 - mn);
            m0 = mn;
            float rs = 0.f;
#pragma unroll
            for (int nt = 0; nt < 8; nt++) {
                sc[nt][0] = exp2f(sc[nt][0] - mn);
                sc[nt][1] = exp2f(sc[nt][1] - mn);
                rs += sc[nt][0] + sc[nt][1];
            }
            rs += __shfl_xor_sync(0xffffffffu, rs, 1);
            rs += __shfl_xor_sync(0xffffffffu, rs, 2);
            l0 = l0 * al + rs;
#pragma unroll
            for (int nt = 0; nt < 8; nt++) { o[nt][0] *= al; o[nt][1] *= al; }
        }
        {
            float mt = -1e30f;
#pragma unroll
            for (int nt = 0; nt < 8; nt++)
                mt = fmaxf(mt, fmaxf(sc[nt][2], sc[nt][3]));
            mt = fmaxf(mt, __shfl_xor_sync(0xffffffffu, mt, 1));
            mt = fmaxf(mt, __shfl_xor_sync(0xffffffffu, mt, 2));
            float mn = fmaxf(m1, mt);
            float al = exp2f(m1 - mn);
            m1 = mn;
            float rs = 0.f;
#pragma unroll
            for (int nt = 0; nt < 8; nt++) {
                sc[nt][2] = exp2f(sc[nt][2] - mn);
                sc[nt][3] = exp2f(sc[nt][3] - mn);
                rs += sc[nt][2] + sc[nt][3];
            }
            rs += __shfl_xor_sync(0xffffffffu, rs, 1);
            rs += __shfl_xor_sync(0xffffffffu, rs, 2);
            l1 = l1 * al + rs;
#pragma unroll
            for (int nt = 0; nt < 8; nt++) { o[nt][2] *= al; o[nt][3] *= al; }
        }

        {
            int R0  = wid * 16 + (lane >> 2);
            int bcl = (lane & 3) * 4;
#pragma unroll
            for (int nt = 0; nt < 8; nt++) {
                __half2 h0 = __floats2half2_rn(sc[nt][0], sc[nt][1]);
                __half2 h1 = __floats2half2_rn(sc[nt][2], sc[nt][3]);
                uint32_t a0 = PS + tile_addr(0, R0,     nt * 16 + bcl);
                uint32_t a1 = PS + tile_addr(0, R0 + 8, nt * 16 + bcl);
                asm volatile("st.shared.b32 [%0], %1;"
                             :: "r"(a0), "r"(*(uint32_t*)&h0));
                asm volatile("st.shared.b32 [%0], %1;"
                             :: "r"(a1), "r"(*(uint32_t*)&h1));
            }
        }
        __syncwarp();

#pragma unroll
        for (int ks = 0; ks < 4; ks++) {
            uint32_t af[4];
            ldsm_x4(PS + tile_addr(0, wid * 16 + a_row_l, ks * 32 + a_bc_l), af);
#pragma unroll
            for (int nt = 0; nt < 8; nt++) {
                uint32_t bv[2];
                ldsm_x2t(VT[buf] + tile_addr(0, ks * 16 + v_row_l, nt * 16), bv);
                mma_f16(o[nt], af, bv[0], bv[1]);
            }
        }
        __syncwarp();
    }

    {
        int    r0 = q0 + wid * 16 + (lane >> 2);
        size_t rowbase = (((size_t)sp * B_ + b) * H_ + h) * S_;
        size_t row0 = rowbase + r0;
        size_t row1 = rowbase + r0 + 8;
        int    cc  = (lane & 3) * 2;
        float* p0 = op + row0 * HD_ + cc;
        float* p1 = op + row1 * HD_ + cc;
#pragma unroll
        for (int nt = 0; nt < 8; nt++) {
            *(float2*)(p0 + nt * 8) = make_float2(o[nt][0], o[nt][1]);
            *(float2*)(p1 + nt * 8) = make_float2(o[nt][2], o[nt][3]);
        }
        if ((lane & 3) == 0) {
            mp[row0] = m0; lp[row0] = l0;
            mp[row1] = m1; lp[row1] = l1;
        }
    }
}

// ---------------------------------------------------------------------------
// Split-KV combine: merge 2 partial-softmax results into fp16 ctx.
// ---------------------------------------------------------------------------
__global__ __launch_bounds__(256)
void attn_combine(const float* __restrict__ op, const float* __restrict__ mp,
                  const float* __restrict__ lp, __half* __restrict__ ctx) {
    int id  = blockIdx.x * 256 + threadIdx.x;
    int row = id >> 4;                  // 0..65535 : ((b*H + h)*S + q)
    int d4  = (id & 15) * 4;

    float m0 = mp[row], m1 = mp[NROWS + row];
    float l0 = lp[row], l1 = lp[NROWS + row];
    float ms = fmaxf(m0, m1);
    float a0 = exp2f(m0 - ms), a1 = exp2f(m1 - ms);
    float li = 1.f / (l0 * a0 + l1 * a1);

    float4 o0 = *(const float4*)(op + (size_t)row * HD_ + d4);
    float4 o1 = *(const float4*)(op + NROWS * HD_ + (size_t)row * HD_ + d4);

    int q = row & (S_ - 1);
    int h = (row >> 11) & (H_ - 1);
    int b = row >> 15;

    __half2 r0 = __floats2half2_rn((o0.x * a0 + o1.x * a1) * li,
                                   (o0.y * a0 + o1.y * a1) * li);
    __half2 r1 = __floats2half2_rn((o0.z * a0 + o1.z * a1) * li,
                                   (o0.w * a0 + o1.w * a1) * li);
    uint2 u;
    u.x = *(uint32_t*)&r0;
    u.y = *(uint32_t*)&r1;
    *(uint2*)(ctx + ((size_t)b * S_ + q) * D_ + h * HD_ + d4) = u;
}

// ---------------------------------------------------------------------------
// Launch
// ---------------------------------------------------------------------------
extern "C" void kernel_launch(void* const* d_in, const int* in_sizes, int n_in,
                              void* d_out, int out_size) {
    const float* x    = (const float*)d_in[0];
    const float* Wqkv = (const float*)d_in[1];
    const float* bqkv = (const float*)d_in[2];
    const float* Wout = (const float*)d_in[3];
    const float* bout = (const float*)d_in[4];
    float* out = (float*)d_out;

    void *qkv_p, *ctx_p, *xt_p, *wq_p, *wo_p, *op_p, *mp_p, *lp_p;
    cudaGetSymbolAddress(&qkv_p, g_qkv16);
    cudaGetSymbolAddress(&ctx_p, g_ctx16);
    cudaGetSymbolAddress(&xt_p,  g_x16);
    cudaGetSymbolAddress(&wq_p,  g_wqkv_t16);
    cudaGetSymbolAddress(&wo_p,  g_wout_t16);
    cudaGetSymbolAddress(&op_p,  g_opart);
    cudaGetSymbolAddress(&mp_p,  g_mpart);
    cudaGetSymbolAddress(&lp_p,  g_lpart);
    __half* qkv16 = (__half*)qkv_p;
    __half* ctx16 = (__half*)ctx_p;
    __half* x16   = (__half*)xt_p;
    __half* wqkvt = (__half*)wq_p;
    __half* woutt = (__half*)wo_p;
    float* op    = (float*)op_p;
    float* mp    = (float*)mp_p;
    float* lp    = (float*)lp_p;

    cudaFuncSetAttribute(gemm_f16, cudaFuncAttributeMaxDynamicSharedMemorySize,
                         GSMEM_BYTES);
    cudaFuncSetAttribute(attn_tc, cudaFuncAttributeMaxDynamicSharedMemorySize,
                         ASMEM_BYTES);

    // Pre-pass: convert x and transposed weights to fp16
    int n4 = MTOT * D_ / 4;
    to_half4<<<(n4 + 255) / 256, 256>>>(x, x16, n4);
    transpose_half<<<dim3(3 * D_ / 32, D_ / 32), dim3(32, 8)>>>(Wqkv, wqkvt, D_, 3 * D_);
    transpose_half<<<dim3(D_ / 32, D_ / 32), dim3(32, 8)>>>(Wout, woutt, D_, D_);

    // 1) QKV projection (fp16 mma) -> fp16 qkv (Q pre-scaled by 0.125*log2e)
    gemm_f16<<<dim3(3 * D_ / 128, MTOT / 128), 256, GSMEM_BYTES>>>(
        x16, wqkvt, bqkv, qkv16, 3 * D_, 2);

    // 2) Attention (fp16 tensor-core flash, split-KV x2) + combine -> fp16 ctx
    attn_tc<<<dim3(S_ / 128, B_ * H_, NSPLIT), 256, ASMEM_BYTES>>>(qkv16, op, mp, lp);
    attn_combine<<<(int)(NROWS * (HD_ / 4) / 256), 256>>>(op, mp, lp, ctx16);

    // 3) Output projection (fp16 mma, fp32 out)
    gemm_f16<<<dim3(D_ / 128, MTOT / 128), 256, GSMEM_BYTES>>>(
        ctx16, woutt, bout, out, D_, 0);
}

// round 16
// speedup vs baseline: 2.3658x; 1.0212x over previous
#include <cuda_runtime.h>
#include <cuda_fp16.h>
#include <stdint.h>
#include <math.h>

#define B_  2
#define S_  2048
#define D_  1024
#define H_  16
#define HD_ 64
#define MTOT (B_ * S_)           // 4096
#define NSPLIT 2
#define SKEYS (S_ / NSPLIT)      // 1024 keys per split
#define NROWS ((size_t)B_ * H_ * S_)   // 65536
#define QSCALE 0.1803368801111117f     // 0.125 * log2(e)

// ---------------------------------------------------------------------------
// Scratch (__device__ globals: allocation-free rule)
// ---------------------------------------------------------------------------
__device__ __half g_qkv16[(size_t)B_ * S_ * 3 * D_];  // fp16 qkv; Q pre-scaled
__device__ __half g_x16[(size_t)MTOT * D_];           // x, fp16
__device__ __half g_wqkv_t16[(size_t)3 * D_ * D_];    // W_qkv^T [3D, D] fp16
__device__ __half g_wout_t16[(size_t)D_ * D_];        // W_out^T [D, D] fp16
__device__ __half g_ctx16[(size_t)B_ * S_ * D_];      // [B,S,D] fp16
// split-KV partials: [split][b][h][S] rows
__device__ float g_opart[(size_t)NSPLIT * NROWS * HD_];   // 32MB
__device__ float g_mpart[(size_t)NSPLIT * NROWS];
__device__ float g_lpart[(size_t)NSPLIT * NROWS];

// ---------------------------------------------------------------------------
// Helpers (baseline-PTX only: cp.async, ldmatrix, mma.sync)
// ---------------------------------------------------------------------------
__device__ __forceinline__ uint32_t smem_u32(const void* p) {
    uint32_t a;
    asm("{ .reg .u64 t; cvta.to.shared.u64 t, %1; cvt.u32.u64 %0, t; }"
        : "=r"(a) : "l"(p));
    return a;
}
__device__ __forceinline__ void cp16(uint32_t dst, const void* src) {
    asm volatile("cp.async.cg.shared.global [%0], [%1], 16;"
                 :: "r"(dst), "l"(src));
}
__device__ __forceinline__ void cp_commit() {
    asm volatile("cp.async.commit_group;");
}
__device__ __forceinline__ void ldsm_x4(uint32_t addr, uint32_t* r) {
    asm volatile("ldmatrix.sync.aligned.m8n8.x4.shared.b16 {%0,%1,%2,%3}, [%4];"
                 : "=r"(r[0]), "=r"(r[1]), "=r"(r[2]), "=r"(r[3]) : "r"(addr));
}
__device__ __forceinline__ void ldsm_x2(uint32_t addr, uint32_t* r) {
    asm volatile("ldmatrix.sync.aligned.m8n8.x2.shared.b16 {%0,%1}, [%2];"
                 : "=r"(r[0]), "=r"(r[1]) : "r"(addr));
}
__device__ __forceinline__ void ldsm_x2t(uint32_t addr, uint32_t* r) {
    asm volatile("ldmatrix.sync.aligned.m8n8.x2.trans.shared.b16 {%0,%1}, [%2];"
                 : "=r"(r[0]), "=r"(r[1]) : "r"(addr));
}
__device__ __forceinline__ void mma_f16(float* c, const uint32_t* a,
                                        uint32_t b0, uint32_t b1) {
    asm volatile(
        "mma.sync.aligned.m16n8k16.row.col.f32.f16.f16.f32 "
        "{%0,%1,%2,%3}, {%4,%5,%6,%7}, {%8,%9}, {%0,%1,%2,%3};"
        : "+f"(c[0]), "+f"(c[1]), "+f"(c[2]), "+f"(c[3])
        : "r"(a[0]), "r"(a[1]), "r"(a[2]), "r"(a[3]), "r"(b0), "r"(b1));
}
__device__ __forceinline__ uint32_t pack_h2(float a, float b) {
    __half2 h = __floats2half2_rn(a, b);
    return *(uint32_t*)&h;
}

// 128B-row tiles (fp16: 64 halves per row)
__device__ __forceinline__ uint32_t tile_addr(uint32_t base, int row, int bc) {
    return base + (uint32_t)(row * 128) + (uint32_t)(bc ^ ((row & 7) << 4));
}

// ---------------------------------------------------------------------------
// Pre-pass kernels: fp32 -> fp16 (RN), and transpose+convert for weights
// ---------------------------------------------------------------------------
__global__ void to_half4(const float* __restrict__ in,
                         __half* __restrict__ out, int n4) {
    int i = blockIdx.x * blockDim.x + threadIdx.x;
    if (i < n4) {
        float4 v = ((const float4*)in)[i];
        __half2 h0 = __floats2half2_rn(v.x, v.y);
        __half2 h1 = __floats2half2_rn(v.z, v.w);
        uint2 u;
        u.x = *(uint32_t*)&h0;
        u.y = *(uint32_t*)&h1;
        ((uint2*)out)[i] = u;
    }
}

// W: [K,N] f32 row-major -> Wt: [N,K] fp16 row-major
__global__ void transpose_half(const float* __restrict__ W,
                               __half* __restrict__ Wt, int K, int N) {
    __shared__ float t[32][33];
    int bx = blockIdx.x * 32;
    int by = blockIdx.y * 32;
    int x = threadIdx.x, y = threadIdx.y;   // block (32, 8)
#pragma unroll
    for (int j = 0; j < 32; j += 8)
        t[y + j][x] = W[(size_t)(by + y + j) * N + bx + x];
    __syncthreads();
#pragma unroll
    for (int j = 0; j < 32; j += 8)
        Wt[(size_t)(bx + y + j) * K + by + x] = __float2half_rn(t[x][y + j]);
}

// ---------------------------------------------------------------------------
// FP16 tensor-core GEMM + bias (m16n8k16, fp32 accum).  (R15, unchanged)
// ---------------------------------------------------------------------------
#define GK    1024
#define BKH   64
#define NKIT  (GK / BKH)         // 16
#define STAGE_BYTES 32768        // A 16KB + B 16KB
#define NSTAGE 3
#define GSMEM_BYTES (NSTAGE * STAGE_BYTES)

__global__ __launch_bounds__(256, 2)
void gemm_f16(const __half* __restrict__ A, const __half* __restrict__ Bt,
              const float* __restrict__ bias, void* __restrict__ Cv, int N,
              int mode) {
    extern __shared__ char smem[];
    uint32_t sbase = smem_u32(smem);

    int tid  = threadIdx.x;
    int wid  = tid >> 5;
    int lane = tid & 31;
    int wm   = wid >> 2;
    int wn   = wid & 3;
    int brow = blockIdx.y * 128;
    int bcol = blockIdx.x * 128;

    uint32_t aB[NSTAGE], bB[NSTAGE];
#pragma unroll
    for (int s = 0; s < NSTAGE; s++) {
        aB[s] = sbase + s * STAGE_BYTES;
        bB[s] = aB[s] + 16384;
    }

    const __half* Agp = A  + (size_t)brow * GK;
    const __half* Bgp = Bt + (size_t)bcol * GK;

    int a_row_l = ((lane >> 3) & 1) * 8 + (lane & 7);
    int a_bc_l  = (lane >> 4) * 16;
    int b_row_l = lane & 7;
    int b_bc_l  = ((lane >> 3) & 1) * 16;

    float acc[4][4][4];
#pragma unroll
    for (int i = 0; i < 4; i++)
#pragma unroll
        for (int j = 0; j < 4; j++)
#pragma unroll
            for (int k = 0; k < 4; k++) acc[i][j][k] = 0.f;

#pragma unroll
    for (int s = 0; s < 2; s++) {
        int k0 = s * BKH;
#pragma unroll
        for (int j = 0; j < 4; j++) {
            int idx = tid + j * 256;
            int row = idx >> 3;
            int c16 = (idx & 7) * 16;
            uint32_t off = tile_addr(0, row, c16);
            cp16(aB[s] + off, Agp + (size_t)row * GK + k0 + (c16 >> 1));
            cp16(bB[s] + off, Bgp + (size_t)row * GK + k0 + (c16 >> 1));
        }
        cp_commit();
    }

    for (int it = 0; it < NKIT; it++) {
        if (it + 1 < NKIT) {
            asm volatile("cp.async.wait_group 1;");
        } else {
            asm volatile("cp.async.wait_group 0;");
        }
        __syncthreads();

        if (it + 2 < NKIT) {
            int s  = (it + 2) % NSTAGE;
            int k0 = (it + 2) * BKH;
#pragma unroll
            for (int j = 0; j < 4; j++) {
                int idx = tid + j * 256;
                int row = idx >> 3;
                int c16 = (idx & 7) * 16;
                uint32_t off = tile_addr(0, row, c16);
                cp16(aB[s] + off, Agp + (size_t)row * GK + k0 + (c16 >> 1));
                cp16(bB[s] + off, Bgp + (size_t)row * GK + k0 + (c16 >> 1));
            }
            cp_commit();
        }

        int buf = it % NSTAGE;
        uint32_t aS = aB[buf], bS = bB[buf];
#pragma unroll
        for (int ks = 0; ks < 4; ks++) {
            uint32_t af[4][4], bf[4][2];
#pragma unroll
            for (int mt = 0; mt < 4; mt++)
                ldsm_x4(tile_addr(aS, wm * 64 + mt * 16 + a_row_l,
                                  ks * 32 + a_bc_l), af[mt]);
#pragma unroll
            for (int nt = 0; nt < 4; nt++)
                ldsm_x2(tile_addr(bS, wn * 32 + nt * 8 + b_row_l,
                                  ks * 32 + b_bc_l), bf[nt]);
#pragma unroll
            for (int mt = 0; mt < 4; mt++)
#pragma unroll
                for (int nt = 0; nt < 4; nt++)
                    mma_f16(acc[mt][nt], af[mt], bf[nt][0], bf[nt][1]);
        }
    }

#pragma unroll
    for (int mt = 0; mt < 4; mt++) {
        int r0 = brow + wm * 64 + mt * 16 + (lane >> 2);
#pragma unroll
        for (int nt = 0; nt < 4; nt++) {
            int c = bcol + wn * 32 + nt * 8 + 2 * (lane & 3);
            float b0 = bias[c], b1 = bias[c + 1];
            float v00 = acc[mt][nt][0] + b0, v01 = acc[mt][nt][1] + b1;
            float v10 = acc[mt][nt][2] + b0, v11 = acc[mt][nt][3] + b1;
            if (mode == 2) {
                float s = (c < D_) ? QSCALE : 1.f;   // Q columns
                __half* C16 = (__half*)Cv;
                *(__half2*)(C16 + (size_t)r0 * N + c) =
                    __floats2half2_rn(v00 * s, v01 * s);
                *(__half2*)(C16 + (size_t)(r0 + 8) * N + c) =
                    __floats2half2_rn(v10 * s, v11 * s);
            } else {
                float* C = (float*)Cv;
                *(float2*)(C + (size_t)r0 * N + c)       = make_float2(v00, v01);
                *(float2*)(C + (size_t)(r0 + 8) * N + c) = make_float2(v10, v11);
            }
        }
    }
}

// ---------------------------------------------------------------------------
// FP16 tensor-core flash attention, SPLIT-KV(2), base-2 softmax.
// CHANGE vs R15: P never touches smem — the QK^T C-fragment is repacked in
// registers (half2) directly as the PV A-fragment (FA2 layout identity):
//   af = { h2(sc[2ks][0,1]), h2(sc[2ks][2,3]),
//          h2(sc[2ks+1][0,1]), h2(sc[2ks+1][2,3]) }  for key block [16ks,+16)
// Removes 16 STS + 4 ldsm_x4 + 2 syncwarp per warp per tile and the
// P-store->P-load dependency chain.
// ---------------------------------------------------------------------------
#define ASMEM_BYTES (16384 + 2 * 8192 + 2 * 8192)

__global__ __launch_bounds__(256, 1)
void attn_tc(const __half* __restrict__ qkv, float* __restrict__ op,
             float* __restrict__ mp, float* __restrict__ lp) {
    extern __shared__ char smem[];
    uint32_t sbase = smem_u32(smem);
    uint32_t PS    = sbase;                                   // Q staging, 16KB
    uint32_t KT[2] = { sbase + 16384, sbase + 16384 + 8192 };
    uint32_t VT[2] = { sbase + 32768, sbase + 32768 + 8192 };

    int tid  = threadIdx.x;
    int wid  = tid >> 5;
    int lane = tid & 31;
    int b    = blockIdx.y >> 4;
    int h    = blockIdx.y & 15;
    int q0   = blockIdx.x * 128;
    int sp   = blockIdx.z;
    int key0 = sp * SKEYS;

    const __half* base = qkv + (size_t)b * S_ * 3 * D_ + h * HD_;

    int a_row_l = ((lane >> 3) & 1) * 8 + (lane & 7);
    int a_bc_l  = (lane >> 4) * 16;
    int b_row_l = lane & 7;
    int b_bc_l  = ((lane >> 3) & 1) * 16;
    int v_row_l = lane & 15;

    // ---- Q -> smem via cp.async (128 rows x 8 chunks = 1024; 4/thread)
    {
#pragma unroll
        for (int j = 0; j < 4; j++) {
            int idx = tid + j * 256;
            int r   = idx >> 3;
            int c16 = (idx & 7) * 16;
            cp16(PS + tile_addr(0, r, c16),
                 base + (size_t)(q0 + r) * (3 * D_) + (c16 >> 1));
        }
        cp_commit();
    }
    // ---- K0/V0 fill
    {
        const __half* kbase = base + (size_t)key0 * (3 * D_) + D_;
        const __half* vbase = kbase + D_;
#pragma unroll
        for (int j = 0; j < 2; j++) {
            int idx = tid + j * 256;
            int r   = idx >> 3;
            int c16 = (idx & 7) * 16;
            cp16(KT[0] + tile_addr(0, r, c16),
                 kbase + (size_t)r * (3 * D_) + (c16 >> 1));
            cp16(VT[0] + tile_addr(0, r, c16),
                 vbase + (size_t)r * (3 * D_) + (c16 >> 1));
        }
        cp_commit();
    }

    asm volatile("cp.async.wait_group 1;");
    __syncthreads();

    uint32_t qf[4][4];
#pragma unroll
    for (int ks = 0; ks < 4; ks++)
        ldsm_x4(PS + tile_addr(0, wid * 16 + a_row_l, ks * 32 + a_bc_l), qf[ks]);

    float m0 = -1e30f, m1 = -1e30f, l0 = 0.f, l1 = 0.f;
    float o[8][4];
#pragma unroll
    for (int nt = 0; nt < 8; nt++)
#pragma unroll
        for (int k = 0; k < 4; k++) o[nt][k] = 0.f;

    const int NT = SKEYS / 64;
    for (int kt = 0; kt < NT; kt++) {
        int buf = kt & 1;
        asm volatile("cp.async.wait_group 0;");
        __syncthreads();

        if (kt + 1 < NT) {
            int nxt = buf ^ 1;
            const __half* kbase = base + (size_t)(key0 + (kt + 1) * 64) * (3 * D_) + D_;
            const __half* vbase = kbase + D_;
#pragma unroll
            for (int j = 0; j < 2; j++) {
                int idx = tid + j * 256;
                int r   = idx >> 3;
                int c16 = (idx & 7) * 16;
                cp16(KT[nxt] + tile_addr(0, r, c16),
                     kbase + (size_t)r * (3 * D_) + (c16 >> 1));
                cp16(VT[nxt] + tile_addr(0, r, c16),
                     vbase + (size_t)r * (3 * D_) + (c16 >> 1));
            }
            cp_commit();
        }

        // ---- QK^T: 4 ks (k16) x 8 nt
        float sc[8][4];
#pragma unroll
        for (int nt = 0; nt < 8; nt++)
#pragma unroll
            for (int k = 0; k < 4; k++) sc[nt][k] = 0.f;

#pragma unroll
        for (int ks = 0; ks < 4; ks++) {
            uint32_t bf[8][2];
#pragma unroll
            for (int nt = 0; nt < 8; nt++)
                ldsm_x2(KT[buf] + tile_addr(0, nt * 8 + b_row_l,
                                            ks * 32 + b_bc_l), bf[nt]);
#pragma unroll
            for (int nt = 0; nt < 8; nt++)
                mma_f16(sc[nt], qf[ks], bf[nt][0], bf[nt][1]);
        }

        // ---- online softmax (base-2; scores already include log2e via Q)
        {
            float mt = -1e30f;
#pragma unroll
            for (int nt = 0; nt < 8; nt++)
                mt = fmaxf(mt, fmaxf(sc[nt][0], sc[nt][1]));
            mt = fmaxf(mt, __shfl_xor_sync(0xffffffffu, mt, 1));
            mt = fmaxf(mt, __shfl_xor_sync(0xffffffffu, mt, 2));
            float mn = fmaxf(m0, mt);
            float al = exp2f(m0 - mn);
            m0 = mn;
            float rs = 0.f;
#pragma unroll
            for (int nt = 0; nt < 8; nt++) {
                sc[nt][0] = exp2f(sc[nt][0] - mn);
                sc[nt][1] = exp2f(sc[nt][1] - mn);
                rs += sc[nt][0] + sc[nt][1];
            }
            rs += __shfl_xor_sync(0xffffffffu, rs, 1);
            rs += __shfl_xor_sync(0xffffffffu, rs, 2);
            l0 = l0 * al + rs;
#pragma unroll
            for (int nt = 0; nt < 8; nt++) { o[nt][0] *= al; o[nt][1] *= al; }
        }
        {
            float mt = -1e30f;
#pragma unroll
            for (int nt = 0; nt < 8; nt++)
                mt = fmaxf(mt, fmaxf(sc[nt][2], sc[nt][3]));
            mt = fmaxf(mt, __shfl_xor_sync(0xffffffffu, mt, 1));
            mt = fmaxf(mt, __shfl_xor_sync(0xffffffffu, mt, 2));
            float mn = fmaxf(m1, mt);
            float al = exp2f(m1 - mn);
            m1 = mn;
            float rs = 0.f;
#pragma unroll
            for (int nt = 0; nt < 8; nt++) {
                sc[nt][2] = exp2f(sc[nt][2] - mn);
                sc[nt][3] = exp2f(sc[nt][3] - mn);
                rs += sc[nt][2] + sc[nt][3];
            }
            rs += __shfl_xor_sync(0xffffffffu, rs, 1);
            rs += __shfl_xor_sync(0xffffffffu, rs, 2);
            l1 = l1 * al + rs;
#pragma unroll
            for (int nt = 0; nt < 8; nt++) { o[nt][2] *= al; o[nt][3] *= al; }
        }

        // ---- O += P @ V : P packed in registers (FA2 fragment identity)
#pragma unroll
        for (int ks = 0; ks < 4; ks++) {
            uint32_t af[4];
            af[0] = pack_h2(sc[2 * ks][0],     sc[2 * ks][1]);
            af[1] = pack_h2(sc[2 * ks][2],     sc[2 * ks][3]);
            af[2] = pack_h2(sc[2 * ks + 1][0], sc[2 * ks + 1][1]);
            af[3] = pack_h2(sc[2 * ks + 1][2], sc[2 * ks + 1][3]);
#pragma unroll
            for (int nt = 0; nt < 8; nt++) {
                uint32_t bv[2];
                ldsm_x2t(VT[buf] + tile_addr(0, ks * 16 + v_row_l, nt * 16), bv);
                mma_f16(o[nt], af, bv[0], bv[1]);
            }
        }
    }

    // ---- epilogue: store UNNORMALIZED o + (m, l) partials
    {
        int    r0 = q0 + wid * 16 + (lane >> 2);
        size_t rowbase = (((size_t)sp * B_ + b) * H_ + h) * S_;
        size_t row0 = rowbase + r0;
        size_t row1 = rowbase + r0 + 8;
        int    cc  = (lane & 3) * 2;
        float* p0 = op + row0 * HD_ + cc;
        float* p1 = op + row1 * HD_ + cc;
#pragma unroll
        for (int nt = 0; nt < 8; nt++) {
            *(float2*)(p0 + nt * 8) = make_float2(o[nt][0], o[nt][1]);
            *(float2*)(p1 + nt * 8) = make_float2(o[nt][2], o[nt][3]);
        }
        if ((lane & 3) == 0) {
            mp[row0] = m0; lp[row0] = l0;
            mp[row1] = m1; lp[row1] = l1;
        }
    }
}

// ---------------------------------------------------------------------------
// Split-KV combine: merge 2 partial-softmax results into fp16 ctx.
// ---------------------------------------------------------------------------
__global__ __launch_bounds__(256)
void attn_combine(const float* __restrict__ op, const float* __restrict__ mp,
                  const float* __restrict__ lp, __half* __restrict__ ctx) {
    int id  = blockIdx.x * 256 + threadIdx.x;
    int row = id >> 4;                  // 0..65535 : ((b*H + h)*S + q)
    int d4  = (id & 15) * 4;

    float m0 = mp[row], m1 = mp[NROWS + row];
    float l0 = lp[row], l1 = lp[NROWS + row];
    float ms = fmaxf(m0, m1);
    float a0 = exp2f(m0 - ms), a1 = exp2f(m1 - ms);
    float li = 1.f / (l0 * a0 + l1 * a1);

    float4 o0 = *(const float4*)(op + (size_t)row * HD_ + d4);
    float4 o1 = *(const float4*)(op + NROWS * HD_ + (size_t)row * HD_ + d4);

    int q = row & (S_ - 1);
    int h = (row >> 11) & (H_ - 1);
    int b = row >> 15;

    __half2 r0 = __floats2half2_rn((o0.x * a0 + o1.x * a1) * li,
                                   (o0.y * a0 + o1.y * a1) * li);
    __half2 r1 = __floats2half2_rn((o0.z * a0 + o1.z * a1) * li,
                                   (o0.w * a0 + o1.w * a1) * li);
    uint2 u;
    u.x = *(uint32_t*)&r0;
    u.y = *(uint32_t*)&r1;
    *(uint2*)(ctx + ((size_t)b * S_ + q) * D_ + h * HD_ + d4) = u;
}

// ---------------------------------------------------------------------------
// Launch
// ---------------------------------------------------------------------------
extern "C" void kernel_launch(void* const* d_in, const int* in_sizes, int n_in,
                              void* d_out, int out_size) {
    const float* x    = (const float*)d_in[0];
    const float* Wqkv = (const float*)d_in[1];
    const float* bqkv = (const float*)d_in[2];
    const float* Wout = (const float*)d_in[3];
    const float* bout = (const float*)d_in[4];
    float* out = (float*)d_out;

    void *qkv_p, *ctx_p, *xt_p, *wq_p, *wo_p, *op_p, *mp_p, *lp_p;
    cudaGetSymbolAddress(&qkv_p, g_qkv16);
    cudaGetSymbolAddress(&ctx_p, g_ctx16);
    cudaGetSymbolAddress(&xt_p,  g_x16);
    cudaGetSymbolAddress(&wq_p,  g_wqkv_t16);
    cudaGetSymbolAddress(&wo_p,  g_wout_t16);
    cudaGetSymbolAddress(&op_p,  g_opart);
    cudaGetSymbolAddress(&mp_p,  g_mpart);
    cudaGetSymbolAddress(&lp_p,  g_lpart);
    __half* qkv16 = (__half*)qkv_p;
    __half* ctx16 = (__half*)ctx_p;
    __half* x16   = (__half*)xt_p;
    __half* wqkvt = (__half*)wq_p;
    __half* woutt = (__half*)wo_p;
    float* op    = (float*)op_p;
    float* mp    = (float*)mp_p;
    float* lp    = (float*)lp_p;

    cudaFuncSetAttribute(gemm_f16, cudaFuncAttributeMaxDynamicSharedMemorySize,
                         GSMEM_BYTES);
    cudaFuncSetAttribute(attn_tc, cudaFuncAttributeMaxDynamicSharedMemorySize,
                         ASMEM_BYTES);

    // Pre-pass: convert x and transposed weights to fp16
    int n4 = MTOT * D_ / 4;
    to_half4<<<(n4 + 255) / 256, 256>>>(x, x16, n4);
    transpose_half<<<dim3(3 * D_ / 32, D_ / 32), dim3(32, 8)>>>(Wqkv, wqkvt, D_, 3 * D_);
    transpose_half<<<dim3(D_ / 32, D_ / 32), dim3(32, 8)>>>(Wout, woutt, D_, D_);

    // 1) QKV projection (fp16 mma) -> fp16 qkv (Q pre-scaled by 0.125*log2e)
    gemm_f16<<<dim3(3 * D_ / 128, MTOT / 128), 256, GSMEM_BYTES>>>(
        x16, wqkvt, bqkv, qkv16, 3 * D_, 2);

    // 2) Attention (fp16 flash, P-in-registers, split-KV x2) + combine
    attn_tc<<<dim3(S_ / 128, B_ * H_, NSPLIT), 256, ASMEM_BYTES>>>(qkv16, op, mp, lp);
    attn_combine<<<(int)(NROWS * (HD_ / 4) / 256), 256>>>(op, mp, lp, ctx16);

    // 3) Output projection (fp16 mma, fp32 out)
    gemm_f16<<<dim3(D_ / 128, MTOT / 128), 256, GSMEM_BYTES>>>(
        ctx16, woutt, bout, out, D_, 0);
}

// round 17
// speedup vs baseline: 2.4816x; 1.0489x over previous
#include <cuda_runtime.h>
#include <cuda_fp16.h>
#include <stdint.h>
#include <math.h>

#define B_  2
#define S_  2048
#define D_  1024
#define H_  16
#define HD_ 64
#define MTOT (B_ * S_)           // 4096
#define NSPLIT 4
#define SKEYS (S_ / NSPLIT)      // 512 keys per split
#define NROWS ((size_t)B_ * H_ * S_)   // 65536
#define QSCALE 0.1803368801111117f     // 0.125 * log2(e)

// ---------------------------------------------------------------------------
// Scratch (__device__ globals: allocation-free rule)
// ---------------------------------------------------------------------------
__device__ __half g_qkv16[(size_t)B_ * S_ * 3 * D_];  // fp16 qkv; Q pre-scaled
__device__ __half g_x16[(size_t)MTOT * D_];           // x, fp16
__device__ __half g_wqkv_t16[(size_t)3 * D_ * D_];    // W_qkv^T [3D, D] fp16
__device__ __half g_wout_t16[(size_t)D_ * D_];        // W_out^T [D, D] fp16
__device__ __half g_ctx16[(size_t)B_ * S_ * D_];      // [B,S,D] fp16
// split-KV partials: [split][b][h][S] rows
__device__ float g_opart[(size_t)NSPLIT * NROWS * HD_];   // 64MB
__device__ float g_mpart[(size_t)NSPLIT * NROWS];
__device__ float g_lpart[(size_t)NSPLIT * NROWS];

// ---------------------------------------------------------------------------
// Helpers (baseline-PTX only: cp.async, ldmatrix, mma.sync)
// ---------------------------------------------------------------------------
__device__ __forceinline__ uint32_t smem_u32(const void* p) {
    uint32_t a;
    asm("{ .reg .u64 t; cvta.to.shared.u64 t, %1; cvt.u32.u64 %0, t; }"
        : "=r"(a) : "l"(p));
    return a;
}
__device__ __forceinline__ void cp16(uint32_t dst, const void* src) {
    asm volatile("cp.async.cg.shared.global [%0], [%1], 16;"
                 :: "r"(dst), "l"(src));
}
__device__ __forceinline__ void cp_commit() {
    asm volatile("cp.async.commit_group;");
}
__device__ __forceinline__ void ldsm_x4(uint32_t addr, uint32_t* r) {
    asm volatile("ldmatrix.sync.aligned.m8n8.x4.shared.b16 {%0,%1,%2,%3}, [%4];"
                 : "=r"(r[0]), "=r"(r[1]), "=r"(r[2]), "=r"(r[3]) : "r"(addr));
}
__device__ __forceinline__ void ldsm_x2(uint32_t addr, uint32_t* r) {
    asm volatile("ldmatrix.sync.aligned.m8n8.x2.shared.b16 {%0,%1}, [%2];"
                 : "=r"(r[0]), "=r"(r[1]) : "r"(addr));
}
__device__ __forceinline__ void ldsm_x2t(uint32_t addr, uint32_t* r) {
    asm volatile("ldmatrix.sync.aligned.m8n8.x2.trans.shared.b16 {%0,%1}, [%2];"
                 : "=r"(r[0]), "=r"(r[1]) : "r"(addr));
}
__device__ __forceinline__ void mma_f16(float* c, const uint32_t* a,
                                        uint32_t b0, uint32_t b1) {
    asm volatile(
        "mma.sync.aligned.m16n8k16.row.col.f32.f16.f16.f32 "
        "{%0,%1,%2,%3}, {%4,%5,%6,%7}, {%8,%9}, {%0,%1,%2,%3};"
        : "+f"(c[0]), "+f"(c[1]), "+f"(c[2]), "+f"(c[3])
        : "r"(a[0]), "r"(a[1]), "r"(a[2]), "r"(a[3]), "r"(b0), "r"(b1));
}
__device__ __forceinline__ uint32_t pack_h2(float a, float b) {
    __half2 h = __floats2half2_rn(a, b);
    return *(uint32_t*)&h;
}

// 128B-row tiles (fp16: 64 halves per row)
__device__ __forceinline__ uint32_t tile_addr(uint32_t base, int row, int bc) {
    return base + (uint32_t)(row * 128) + (uint32_t)(bc ^ ((row & 7) << 4));
}

// ---------------------------------------------------------------------------
// Pre-pass kernels: fp32 -> fp16 (RN), and transpose+convert for weights
// ---------------------------------------------------------------------------
__global__ void to_half4(const float* __restrict__ in,
                         __half* __restrict__ out, int n4) {
    int i = blockIdx.x * blockDim.x + threadIdx.x;
    if (i < n4) {
        float4 v = ((const float4*)in)[i];
        __half2 h0 = __floats2half2_rn(v.x, v.y);
        __half2 h1 = __floats2half2_rn(v.z, v.w);
        uint2 u;
        u.x = *(uint32_t*)&h0;
        u.y = *(uint32_t*)&h1;
        ((uint2*)out)[i] = u;
    }
}

// W: [K,N] f32 row-major -> Wt: [N,K] fp16 row-major
__global__ void transpose_half(const float* __restrict__ W,
                               __half* __restrict__ Wt, int K, int N) {
    __shared__ float t[32][33];
    int bx = blockIdx.x * 32;
    int by = blockIdx.y * 32;
    int x = threadIdx.x, y = threadIdx.y;   // block (32, 8)
#pragma unroll
    for (int j = 0; j < 32; j += 8)
        t[y + j][x] = W[(size_t)(by + y + j) * N + bx + x];
    __syncthreads();
#pragma unroll
    for (int j = 0; j < 32; j += 8)
        Wt[(size_t)(bx + y + j) * K + by + x] = __float2half_rn(t[x][y + j]);
}

// ---------------------------------------------------------------------------
// FP16 tensor-core GEMM + bias (m16n8k16, fp32 accum).  (R15, unchanged)
// ---------------------------------------------------------------------------
#define GK    1024
#define BKH   64
#define NKIT  (GK / BKH)         // 16
#define STAGE_BYTES 32768        // A 16KB + B 16KB
#define NSTAGE 3
#define GSMEM_BYTES (NSTAGE * STAGE_BYTES)

__global__ __launch_bounds__(256, 2)
void gemm_f16(const __half* __restrict__ A, const __half* __restrict__ Bt,
              const float* __restrict__ bias, void* __restrict__ Cv, int N,
              int mode) {
    extern __shared__ char smem[];
    uint32_t sbase = smem_u32(smem);

    int tid  = threadIdx.x;
    int wid  = tid >> 5;
    int lane = tid & 31;
    int wm   = wid >> 2;
    int wn   = wid & 3;
    int brow = blockIdx.y * 128;
    int bcol = blockIdx.x * 128;

    uint32_t aB[NSTAGE], bB[NSTAGE];
#pragma unroll
    for (int s = 0; s < NSTAGE; s++) {
        aB[s] = sbase + s * STAGE_BYTES;
        bB[s] = aB[s] + 16384;
    }

    const __half* Agp = A  + (size_t)brow * GK;
    const __half* Bgp = Bt + (size_t)bcol * GK;

    int a_row_l = ((lane >> 3) & 1) * 8 + (lane & 7);
    int a_bc_l  = (lane >> 4) * 16;
    int b_row_l = lane & 7;
    int b_bc_l  = ((lane >> 3) & 1) * 16;

    float acc[4][4][4];
#pragma unroll
    for (int i = 0; i < 4; i++)
#pragma unroll
        for (int j = 0; j < 4; j++)
#pragma unroll
            for (int k = 0; k < 4; k++) acc[i][j][k] = 0.f;

#pragma unroll
    for (int s = 0; s < 2; s++) {
        int k0 = s * BKH;
#pragma unroll
        for (int j = 0; j < 4; j++) {
            int idx = tid + j * 256;
            int row = idx >> 3;
            int c16 = (idx & 7) * 16;
            uint32_t off = tile_addr(0, row, c16);
            cp16(aB[s] + off, Agp + (size_t)row * GK + k0 + (c16 >> 1));
            cp16(bB[s] + off, Bgp + (size_t)row * GK + k0 + (c16 >> 1));
        }
        cp_commit();
    }

    for (int it = 0; it < NKIT; it++) {
        if (it + 1 < NKIT) {
            asm volatile("cp.async.wait_group 1;");
        } else {
            asm volatile("cp.async.wait_group 0;");
        }
        __syncthreads();

        if (it + 2 < NKIT) {
            int s  = (it + 2) % NSTAGE;
            int k0 = (it + 2) * BKH;
#pragma unroll
            for (int j = 0; j < 4; j++) {
                int idx = tid + j * 256;
                int row = idx >> 3;
                int c16 = (idx & 7) * 16;
                uint32_t off = tile_addr(0, row, c16);
                cp16(aB[s] + off, Agp + (size_t)row * GK + k0 + (c16 >> 1));
                cp16(bB[s] + off, Bgp + (size_t)row * GK + k0 + (c16 >> 1));
            }
            cp_commit();
        }

        int buf = it % NSTAGE;
        uint32_t aS = aB[buf], bS = bB[buf];
#pragma unroll
        for (int ks = 0; ks < 4; ks++) {
            uint32_t af[4][4], bf[4][2];
#pragma unroll
            for (int mt = 0; mt < 4; mt++)
                ldsm_x4(tile_addr(aS, wm * 64 + mt * 16 + a_row_l,
                                  ks * 32 + a_bc_l), af[mt]);
#pragma unroll
            for (int nt = 0; nt < 4; nt++)
                ldsm_x2(tile_addr(bS, wn * 32 + nt * 8 + b_row_l,
                                  ks * 32 + b_bc_l), bf[nt]);
#pragma unroll
            for (int mt = 0; mt < 4; mt++)
#pragma unroll
                for (int nt = 0; nt < 4; nt++)
                    mma_f16(acc[mt][nt], af[mt], bf[nt][0], bf[nt][1]);
        }
    }

#pragma unroll
    for (int mt = 0; mt < 4; mt++) {
        int r0 = brow + wm * 64 + mt * 16 + (lane >> 2);
#pragma unroll
        for (int nt = 0; nt < 4; nt++) {
            int c = bcol + wn * 32 + nt * 8 + 2 * (lane & 3);
            float b0 = bias[c], b1 = bias[c + 1];
            float v00 = acc[mt][nt][0] + b0, v01 = acc[mt][nt][1] + b1;
            float v10 = acc[mt][nt][2] + b0, v11 = acc[mt][nt][3] + b1;
            if (mode == 2) {
                float s = (c < D_) ? QSCALE : 1.f;   // Q columns
                __half* C16 = (__half*)Cv;
                *(__half2*)(C16 + (size_t)r0 * N + c) =
                    __floats2half2_rn(v00 * s, v01 * s);
                *(__half2*)(C16 + (size_t)(r0 + 8) * N + c) =
                    __floats2half2_rn(v10 * s, v11 * s);
            } else {
                float* C = (float*)Cv;
                *(float2*)(C + (size_t)r0 * N + c)       = make_float2(v00, v01);
                *(float2*)(C + (size_t)(r0 + 8) * N + c) = make_float2(v10, v11);
            }
        }
    }
}

// ---------------------------------------------------------------------------
// FP16 tensor-core flash attention, SPLIT-KV(4), base-2 softmax,
// P-in-registers (FA2 identity). CHANGE vs R16: occ 2 (__launch_bounds__
// (256,2); fp16 kernel live regs ~120 <= 128 cap, smem 48KB -> 96KB/SM)
// + NSPLIT 2->4 so waves stay quantization-free (2048 CTAs / 296 slots
// = 6.92 -> 7 waves, 98.8%).
// ---------------------------------------------------------------------------
#define ASMEM_BYTES (16384 + 2 * 8192 + 2 * 8192)

__global__ __launch_bounds__(256, 2)
void attn_tc(const __half* __restrict__ qkv, float* __restrict__ op,
             float* __restrict__ mp, float* __restrict__ lp) {
    extern __shared__ char smem[];
    uint32_t sbase = smem_u32(smem);
    uint32_t PS    = sbase;                                   // Q staging, 16KB
    uint32_t KT[2] = { sbase + 16384, sbase + 16384 + 8192 };
    uint32_t VT[2] = { sbase + 32768, sbase + 32768 + 8192 };

    int tid  = threadIdx.x;
    int wid  = tid >> 5;
    int lane = tid & 31;
    int b    = blockIdx.y >> 4;
    int h    = blockIdx.y & 15;
    int q0   = blockIdx.x * 128;
    int sp   = blockIdx.z;
    int key0 = sp * SKEYS;

    const __half* base = qkv + (size_t)b * S_ * 3 * D_ + h * HD_;

    int a_row_l = ((lane >> 3) & 1) * 8 + (lane & 7);
    int a_bc_l  = (lane >> 4) * 16;
    int b_row_l = lane & 7;
    int b_bc_l  = ((lane >> 3) & 1) * 16;
    int v_row_l = lane & 15;

    // ---- Q -> smem via cp.async (128 rows x 8 chunks = 1024; 4/thread)
    {
#pragma unroll
        for (int j = 0; j < 4; j++) {
            int idx = tid + j * 256;
            int r   = idx >> 3;
            int c16 = (idx & 7) * 16;
            cp16(PS + tile_addr(0, r, c16),
                 base + (size_t)(q0 + r) * (3 * D_) + (c16 >> 1));
        }
        cp_commit();
    }
    // ---- K0/V0 fill
    {
        const __half* kbase = base + (size_t)key0 * (3 * D_) + D_;
        const __half* vbase = kbase + D_;
#pragma unroll
        for (int j = 0; j < 2; j++) {
            int idx = tid + j * 256;
            int r   = idx >> 3;
            int c16 = (idx & 7) * 16;
            cp16(KT[0] + tile_addr(0, r, c16),
                 kbase + (size_t)r * (3 * D_) + (c16 >> 1));
            cp16(VT[0] + tile_addr(0, r, c16),
                 vbase + (size_t)r * (3 * D_) + (c16 >> 1));
        }
        cp_commit();
    }

    asm volatile("cp.async.wait_group 1;");
    __syncthreads();

    uint32_t qf[4][4];
#pragma unroll
    for (int ks = 0; ks < 4; ks++)
        ldsm_x4(PS + tile_addr(0, wid * 16 + a_row_l, ks * 32 + a_bc_l), qf[ks]);

    float m0 = -1e30f, m1 = -1e30f, l0 = 0.f, l1 = 0.f;
    float o[8][4];
#pragma unroll
    for (int nt = 0; nt < 8; nt++)
#pragma unroll
        for (int k = 0; k < 4; k++) o[nt][k] = 0.f;

    const int NT = SKEYS / 64;   // 8 tiles per split
    for (int kt = 0; kt < NT; kt++) {
        int buf = kt & 1;
        asm volatile("cp.async.wait_group 0;");
        __syncthreads();

        if (kt + 1 < NT) {
            int nxt = buf ^ 1;
            const __half* kbase = base + (size_t)(key0 + (kt + 1) * 64) * (3 * D_) + D_;
            const __half* vbase = kbase + D_;
#pragma unroll
            for (int j = 0; j < 2; j++) {
                int idx = tid + j * 256;
                int r   = idx >> 3;
                int c16 = (idx & 7) * 16;
                cp16(KT[nxt] + tile_addr(0, r, c16),
                     kbase + (size_t)r * (3 * D_) + (c16 >> 1));
                cp16(VT[nxt] + tile_addr(0, r, c16),
                     vbase + (size_t)r * (3 * D_) + (c16 >> 1));
            }
            cp_commit();
        }

        // ---- QK^T: 4 ks (k16) x 8 nt
        float sc[8][4];
#pragma unroll
        for (int nt = 0; nt < 8; nt++)
#pragma unroll
            for (int k = 0; k < 4; k++) sc[nt][k] = 0.f;

#pragma unroll
        for (int ks = 0; ks < 4; ks++) {
            uint32_t bf[8][2];
#pragma unroll
            for (int nt = 0; nt < 8; nt++)
                ldsm_x2(KT[buf] + tile_addr(0, nt * 8 + b_row_l,
                                            ks * 32 + b_bc_l), bf[nt]);
#pragma unroll
            for (int nt = 0; nt < 8; nt++)
                mma_f16(sc[nt], qf[ks], bf[nt][0], bf[nt][1]);
        }

        // ---- online softmax (base-2; scores already include log2e via Q)
        {
            float mt = -1e30f;
#pragma unroll
            for (int nt = 0; nt < 8; nt++)
                mt = fmaxf(mt, fmaxf(sc[nt][0], sc[nt][1]));
            mt = fmaxf(mt, __shfl_xor_sync(0xffffffffu, mt, 1));
            mt = fmaxf(mt, __shfl_xor_sync(0xffffffffu, mt, 2));
            float mn = fmaxf(m0, mt);
            float al = exp2f(m0 - mn);
            m0 = mn;
            float rs = 0.f;
#pragma unroll
            for (int nt = 0; nt < 8; nt++) {
                sc[nt][0] = exp2f(sc[nt][0] - mn);
                sc[nt][1] = exp2f(sc[nt][1] - mn);
                rs += sc[nt][0] + sc[nt][1];
            }
            rs += __shfl_xor_sync(0xffffffffu, rs, 1);
            rs += __shfl_xor_sync(0xffffffffu, rs, 2);
            l0 = l0 * al + rs;
#pragma unroll
            for (int nt = 0; nt < 8; nt++) { o[nt][0] *= al; o[nt][1] *= al; }
        }
        {
            float mt = -1e30f;
#pragma unroll
            for (int nt = 0; nt < 8; nt++)
                mt = fmaxf(mt, fmaxf(sc[nt][2], sc[nt][3]));
            mt = fmaxf(mt, __shfl_xor_sync(0xffffffffu, mt, 1));
            mt = fmaxf(mt, __shfl_xor_sync(0xffffffffu, mt, 2));
            float mn = fmaxf(m1, mt);
            float al = exp2f(m1 - mn);
            m1 = mn;
            float rs = 0.f;
#pragma unroll
            for (int nt = 0; nt < 8; nt++) {
                sc[nt][2] = exp2f(sc[nt][2] - mn);
                sc[nt][3] = exp2f(sc[nt][3] - mn);
                rs += sc[nt][2] + sc[nt][3];
            }
            rs += __shfl_xor_sync(0xffffffffu, rs, 1);
            rs += __shfl_xor_sync(0xffffffffu, rs, 2);
            l1 = l1 * al + rs;
#pragma unroll
            for (int nt = 0; nt < 8; nt++) { o[nt][2] *= al; o[nt][3] *= al; }
        }

        // ---- O += P @ V : P packed in registers (FA2 fragment identity)
#pragma unroll
        for (int ks = 0; ks < 4; ks++) {
            uint32_t af[4];
            af[0] = pack_h2(sc[2 * ks][0],     sc[2 * ks][1]);
            af[1] = pack_h2(sc[2 * ks][2],     sc[2 * ks][3]);
            af[2] = pack_h2(sc[2 * ks + 1][0], sc[2 * ks + 1][1]);
            af[3] = pack_h2(sc[2 * ks + 1][2], sc[2 * ks + 1][3]);
#pragma unroll
            for (int nt = 0; nt < 8; nt++) {
                uint32_t bv[2];
                ldsm_x2t(VT[buf] + tile_addr(0, ks * 16 + v_row_l, nt * 16), bv);
                mma_f16(o[nt], af, bv[0], bv[1]);
            }
        }
    }

    // ---- epilogue: store UNNORMALIZED o + (m, l) partials
    {
        int    r0 = q0 + wid * 16 + (lane >> 2);
        size_t rowbase = (((size_t)sp * B_ + b) * H_ + h) * S_;
        size_t row0 = rowbase + r0;
        size_t row1 = rowbase + r0 + 8;
        int    cc  = (lane & 3) * 2;
        float* p0 = op + row0 * HD_ + cc;
        float* p1 = op + row1 * HD_ + cc;
#pragma unroll
        for (int nt = 0; nt < 8; nt++) {
            *(float2*)(p0 + nt * 8) = make_float2(o[nt][0], o[nt][1]);
            *(float2*)(p1 + nt * 8) = make_float2(o[nt][2], o[nt][3]);
        }
        if ((lane & 3) == 0) {
            mp[row0] = m0; lp[row0] = l0;
            mp[row1] = m1; lp[row1] = l1;
        }
    }
}

// ---------------------------------------------------------------------------
// Split-KV combine: merge NSPLIT partial-softmax results into fp16 ctx.
// ---------------------------------------------------------------------------
__global__ __launch_bounds__(256)
void attn_combine(const float* __restrict__ op, const float* __restrict__ mp,
                  const float* __restrict__ lp, __half* __restrict__ ctx) {
    int id  = blockIdx.x * 256 + threadIdx.x;
    int row = id >> 4;                  // 0..65535 : ((b*H + h)*S + q)
    int d4  = (id & 15) * 4;

    float m[NSPLIT], l[NSPLIT];
    float ms = -1e30f;
#pragma unroll
    for (int s = 0; s < NSPLIT; s++) {
        m[s] = mp[(size_t)s * NROWS + row];
        l[s] = lp[(size_t)s * NROWS + row];
        ms = fmaxf(ms, m[s]);
    }
    float a[NSPLIT];
    float lsum = 0.f;
#pragma unroll
    for (int s = 0; s < NSPLIT; s++) {
        a[s] = exp2f(m[s] - ms);
        lsum += l[s] * a[s];
    }
    float li = 1.f / lsum;

    float ox = 0.f, oy = 0.f, oz = 0.f, ow = 0.f;
#pragma unroll
    for (int s = 0; s < NSPLIT; s++) {
        float4 v = *(const float4*)(op + (size_t)s * NROWS * HD_
                                    + (size_t)row * HD_ + d4);
        ox += v.x * a[s]; oy += v.y * a[s];
        oz += v.z * a[s]; ow += v.w * a[s];
    }

    int q = row & (S_ - 1);
    int h = (row >> 11) & (H_ - 1);
    int b = row >> 15;

    __half2 r0 = __floats2half2_rn(ox * li, oy * li);
    __half2 r1 = __floats2half2_rn(oz * li, ow * li);
    uint2 u;
    u.x = *(uint32_t*)&r0;
    u.y = *(uint32_t*)&r1;
    *(uint2*)(ctx + ((size_t)b * S_ + q) * D_ + h * HD_ + d4) = u;
}

// ---------------------------------------------------------------------------
// Launch
// ---------------------------------------------------------------------------
extern "C" void kernel_launch(void* const* d_in, const int* in_sizes, int n_in,
                              void* d_out, int out_size) {
    const float* x    = (const float*)d_in[0];
    const float* Wqkv = (const float*)d_in[1];
    const float* bqkv = (const float*)d_in[2];
    const float* Wout = (const float*)d_in[3];
    const float* bout = (const float*)d_in[4];
    float* out = (float*)d_out;

    void *qkv_p, *ctx_p, *xt_p, *wq_p, *wo_p, *op_p, *mp_p, *lp_p;
    cudaGetSymbolAddress(&qkv_p, g_qkv16);
    cudaGetSymbolAddress(&ctx_p, g_ctx16);
    cudaGetSymbolAddress(&xt_p,  g_x16);
    cudaGetSymbolAddress(&wq_p,  g_wqkv_t16);
    cudaGetSymbolAddress(&wo_p,  g_wout_t16);
    cudaGetSymbolAddress(&op_p,  g_opart);
    cudaGetSymbolAddress(&mp_p,  g_mpart);
    cudaGetSymbolAddress(&lp_p,  g_lpart);
    __half* qkv16 = (__half*)qkv_p;
    __half* ctx16 = (__half*)ctx_p;
    __half* x16   = (__half*)xt_p;
    __half* wqkvt = (__half*)wq_p;
    __half* woutt = (__half*)wo_p;
    float* op    = (float*)op_p;
    float* mp    = (float*)mp_p;
    float* lp    = (float*)lp_p;

    cudaFuncSetAttribute(gemm_f16, cudaFuncAttributeMaxDynamicSharedMemorySize,
                         GSMEM_BYTES);
    cudaFuncSetAttribute(attn_tc, cudaFuncAttributeMaxDynamicSharedMemorySize,
                         ASMEM_BYTES);

    // Pre-pass: convert x and transposed weights to fp16
    int n4 = MTOT * D_ / 4;
    to_half4<<<(n4 + 255) / 256, 256>>>(x, x16, n4);
    transpose_half<<<dim3(3 * D_ / 32, D_ / 32), dim3(32, 8)>>>(Wqkv, wqkvt, D_, 3 * D_);
    transpose_half<<<dim3(D_ / 32, D_ / 32), dim3(32, 8)>>>(Wout, woutt, D_, D_);

    // 1) QKV projection (fp16 mma) -> fp16 qkv (Q pre-scaled by 0.125*log2e)
    gemm_f16<<<dim3(3 * D_ / 128, MTOT / 128), 256, GSMEM_BYTES>>>(
        x16, wqkvt, bqkv, qkv16, 3 * D_, 2);

    // 2) Attention (fp16 flash, P-in-registers, split-KV x4, occ 2) + combine
    attn_tc<<<dim3(S_ / 128, B_ * H_, NSPLIT), 256, ASMEM_BYTES>>>(qkv16, op, mp, lp);
    attn_combine<<<(int)(NROWS * (HD_ / 4) / 256), 256>>>(op, mp, lp, ctx16);

    // 3) Output projection (fp16 mma, fp32 out)
    gemm_f16<<<dim3(D_ / 128, MTOT / 128), 256, GSMEM_BYTES>>>(
        ctx16, woutt, bout, out, D_, 0);
}